// round 13
// baseline (speedup 1.0000x reference)
#include <cuda_runtime.h>
#include <cuda_bf16.h>
#include <cuda_fp16.h>
#include <cstdint>

#define Bn 8
#define Nn 1024
#define En 256
#define Hn 8
#define Dn 32
#define Cn 4

#define QSZ (Bn * Hn * Nn * Dn)            // 2M elems
__device__ __half g_xh[Bn * Nn * En];
__device__ __half g_qh[QSZ];
__device__ __half g_kh[QSZ];
__device__ __half g_vth[QSZ];              // [B,H,D,N]
__device__ __half g_ch[Bn * Nn * En];      // ctx row-major
__device__ __half g_wth[4 * En * En];      // W^T: q,k,v,o
__device__ uint8_t g_bias8[(size_t)Bn * Hn * Nn * Nn]; // 67MB e4m3, log2e-scaled

#define SCALEQ 0.25506807163967554f   // 1/sqrt(32) * log2e
#define LOG2E  1.4426950408889634f

__device__ __forceinline__ float ex2(float x) {
    float y;
    asm("ex2.approx.f32 %0, %1;" : "=f"(y) : "f"(x));
    return y;
}
__device__ __forceinline__ uint32_t bitsh2(__half2 v) {
    return *reinterpret_cast<uint32_t*>(&v);
}
__device__ __forceinline__ uint2 pack4h(float a, float b, float c, float d) {
    uint2 r;
    r.x = bitsh2(__floats2half2_rn(a, b));
    r.y = bitsh2(__floats2half2_rn(c, d));
    return r;
}
__device__ __forceinline__ uint32_t smem_u32(const void* p) {
    uint32_t a;
    asm("{ .reg .u64 t; cvta.to.shared.u64 t, %1; cvt.u32.u64 %0, t; }" : "=r"(a) : "l"(p));
    return a;
}
// pack two floats -> e4m3x2 (memory order: lo byte = second operand)
__device__ __forceinline__ uint16_t pk_e4m3(float hi, float lo) {
    uint16_t r;
    asm("cvt.rn.satfinite.e4m3x2.f32 %0, %1, %2;" : "=h"(r) : "f"(hi), "f"(lo));
    return r;
}

#define CP_A16(d, s) asm volatile("cp.async.cg.shared.global [%0], [%1], 16;" :: "r"(d), "l"(s) : "memory")
#define CP_COMMIT()  asm volatile("cp.async.commit_group;" ::: "memory")
#define CP_WAIT0()   asm volatile("cp.async.wait_group 0;" ::: "memory")
#define CP_WAIT1()   asm volatile("cp.async.wait_group 1;" ::: "memory")

#define MMAH(c, a, b0, b1)                                                    \
    asm volatile("mma.sync.aligned.m16n8k16.row.col.f32.f16.f16.f32 "         \
        "{%0,%1,%2,%3}, {%4,%5,%6,%7}, {%8,%9}, {%0,%1,%2,%3};"               \
        : "+f"((c)[0]), "+f"((c)[1]), "+f"((c)[2]), "+f"((c)[3])              \
        : "r"((a)[0]), "r"((a)[1]), "r"((a)[2]), "r"((a)[3]), "r"(b0), "r"(b1))

// ============================================================================
// convert x -> fp16
// ============================================================================
__global__ __launch_bounds__(256)
void convert_x(const float* __restrict__ x)
{
    int i = blockIdx.x * 256 + threadIdx.x;   // per float4
    float4 v = ((const float4*)x)[i];
    ((uint2*)g_xh)[i] = pack4h(v.x, v.y, v.z, v.w);
}

// ============================================================================
// convert W -> W^T fp16 (32x32 tiles)
// ============================================================================
__global__ __launch_bounds__(256)
void convert_wt(const float* __restrict__ W0, const float* __restrict__ W1,
                const float* __restrict__ W2, const float* __restrict__ W3)
{
    __shared__ float T[32][33];
    const int z = blockIdx.x >> 6;
    const int tile = blockIdx.x & 63;
    const int k0 = (tile >> 3) * 32;
    const int n0 = (tile & 7) * 32;
    const float* W = (z == 0) ? W0 : (z == 1) ? W1 : (z == 2) ? W2 : W3;
    const int tid = threadIdx.x;
    {
        int r = tid >> 3, c4 = tid & 7;
        float4 v = *(const float4*)&W[(k0 + r) * En + n0 + c4 * 4];
        T[r][c4 * 4 + 0] = v.x; T[r][c4 * 4 + 1] = v.y;
        T[r][c4 * 4 + 2] = v.z; T[r][c4 * 4 + 3] = v.w;
    }
    __syncthreads();
    {
        int r = tid >> 3, c4 = tid & 7;
        int off = z * En * En + (n0 + r) * En + k0 + c4 * 4;
        *(uint2*)&g_wth[off] = pack4h(T[c4 * 4 + 0][r], T[c4 * 4 + 1][r],
                                      T[c4 * 4 + 2][r], T[c4 * 4 + 3][r]);
    }
}

// ============================================================================
// fp16 tensor-core GEMM, cp.async double-buffered.
// MODE 0: QKV (z=blockIdx.z; epilogue -> fp16 Q(scaled)/K; V transposed+fp16
//          through smem restage -> g_vth [B,H,D,N])
// MODE 1: out-proj (A=g_ch, W slot 3; epilogue -> +bo +x -> out fp32)
// ============================================================================
#define GBUF_W 3840          // per buffer: A@0 (2560) + B@2560 (1280)
#define GB_OFF 2560

template <int MODE>
__global__ __launch_bounds__(256)
void gemm_tc(const float* __restrict__ bias0, const float* __restrict__ bias1,
             const float* __restrict__ bias2,
             const float* __restrict__ X, float* __restrict__ OutR, int yoff)
{
    __shared__ __align__(16) uint32_t S[2 * GBUF_W];   // 30 KB
    const uint32_t sb = smem_u32(S);
    const int tid = threadIdx.x;
    const int w = tid >> 5, lane = tid & 31;
    const int g = lane >> 2, t = lane & 3;
    const int row0 = (blockIdx.y + yoff) * 128;
    const int col0 = blockIdx.x * 64;
    const int z = (MODE == 0) ? blockIdx.z : 3;

    const uint4* a4p = (const uint4*)((MODE == 0) ? g_xh : g_ch);
    const uint4* b4p = (const uint4*)(g_wth + z * En * En);

    float c_[8][4] = {};

    const int a_row = tid >> 1;          // 0..127
    const int a_c4 = (tid & 1) * 2;      // uint4 col 0/2
    const int b_row = tid >> 2;          // 0..63
    const int b_c4 = tid & 3;

    auto stage = [&](int kc, int bb) {
        size_t siA = (size_t)(row0 + a_row) * 32 + kc * 4 + a_c4;
        CP_A16(sb + (bb + a_row * 20 + a_c4 * 4) * 4, a4p + siA);
        CP_A16(sb + (bb + a_row * 20 + (a_c4 + 1) * 4) * 4, a4p + siA + 1);
        size_t siB = (size_t)(col0 + b_row) * 32 + kc * 4 + b_c4;
        CP_A16(sb + (bb + GB_OFF + b_row * 20 + b_c4 * 4) * 4, b4p + siB);
        CP_COMMIT();
    };

    stage(0, 0);
    for (int kc = 0; kc < 8; kc++) {
        const int bb = (kc & 1) * GBUF_W;
        if (kc + 1 < 8) {
            stage(kc + 1, ((kc + 1) & 1) * GBUF_W);
            CP_WAIT1();
        } else {
            CP_WAIT0();
        }
        __syncthreads();
#pragma unroll
        for (int kt = 0; kt < 2; kt++) {
            const int aw = bb + (w * 16 + g) * 20 + kt * 8 + t;
            uint32_t a[4];
            a[0] = S[aw];       a[1] = S[aw + 160];
            a[2] = S[aw + 4];   a[3] = S[aw + 164];
#pragma unroll
            for (int nt = 0; nt < 8; nt++) {
                const int kw = bb + GB_OFF + (nt * 8 + g) * 20 + kt * 8 + t;
                MMAH(c_[nt], a, S[kw], S[kw + 4]);
            }
        }
        __syncthreads();
    }

    const int m = row0 + w * 16 + g;
    if (MODE == 0) {
        const float* bias = (z == 0) ? bias0 : (z == 1) ? bias1 : bias2;
        const int b = row0 >> 10, n0 = row0 & 1023;
        const int n = m & 1023;
        if (z < 2) {
#pragma unroll
            for (int nt = 0; nt < 8; nt++) {
                int col = col0 + nt * 8 + 2 * t;
                float bz0 = bias[col], bz1 = bias[col + 1];
                float v0 = c_[nt][0] + bz0, v1 = c_[nt][1] + bz1;
                float v2 = c_[nt][2] + bz0, v3 = c_[nt][3] + bz1;
                int h = col >> 5, dd = col & 31;
                size_t oA = ((size_t)(b * Hn + h) * Nn + n) * Dn + dd;
                size_t oB = oA + 8 * Dn;
                if (z == 0) {
                    v0 *= SCALEQ; v1 *= SCALEQ; v2 *= SCALEQ; v3 *= SCALEQ;
                    *(uint32_t*)&g_qh[oA] = bitsh2(__floats2half2_rn(v0, v1));
                    *(uint32_t*)&g_qh[oB] = bitsh2(__floats2half2_rn(v2, v3));
                } else {
                    *(uint32_t*)&g_kh[oA] = bitsh2(__floats2half2_rn(v0, v1));
                    *(uint32_t*)&g_kh[oB] = bitsh2(__floats2half2_rn(v2, v3));
                }
            }
        } else {
            // V: transpose through smem (k-loop done; S reusable) -> g_vth [B,H,D,N]
            __half* S2 = (__half*)S;
            const int lr = w * 16 + g;
#pragma unroll
            for (int nt = 0; nt < 8; nt++) {
                int lc = nt * 8 + 2 * t;
                int col = col0 + lc;
                float bz0 = bias[col], bz1 = bias[col + 1];
                S2[lc * 136 + lr]           = __float2half_rn(c_[nt][0] + bz0);
                S2[(lc + 1) * 136 + lr]     = __float2half_rn(c_[nt][1] + bz1);
                S2[lc * 136 + lr + 8]       = __float2half_rn(c_[nt][2] + bz0);
                S2[(lc + 1) * 136 + lr + 8] = __float2half_rn(c_[nt][3] + bz1);
            }
            __syncthreads();
            const int colx = tid >> 2, seg = tid & 3;
            const int gc = col0 + colx;
            const int h = gc >> 5, dd = gc & 31;
            size_t dst = ((size_t)(b * Hn + h) * Dn + dd) * Nn + n0 + seg * 32;
            const uint4* sp = (const uint4*)&S2[colx * 136 + seg * 32];
            uint4* dp = (uint4*)&g_vth[dst];
            dp[0] = sp[0]; dp[1] = sp[1]; dp[2] = sp[2]; dp[3] = sp[3];
        }
    } else {
#pragma unroll
        for (int nt = 0; nt < 8; nt++) {
            int col = col0 + nt * 8 + 2 * t;
            float bz0 = bias0[col], bz1 = bias0[col + 1];
            float2 xA = *(const float2*)&X[(size_t)m * En + col];
            float2 xB = *(const float2*)&X[(size_t)(m + 8) * En + col];
            float2 oA = {c_[nt][0] + bz0 + xA.x, c_[nt][1] + bz1 + xA.y};
            float2 oB = {c_[nt][2] + bz0 + xB.x, c_[nt][3] + bz1 + xB.y};
            *(float2*)&OutR[(size_t)m * En + col] = oA;
            *(float2*)&OutR[(size_t)(m + 8) * En + col] = oB;
        }
    }
}

// ============================================================================
// bias precompute -> e4m3 fp8, log2e-scaled.  Half-batch per launch (b0).
// ============================================================================
__global__ __launch_bounds__(256)
void bias_pre(const float* __restrict__ adj, const float* __restrict__ Wa,
              const float* __restrict__ ba, int b0)
{
    __shared__ float ws[Cn * Hn];
    __shared__ float offs[Hn];
    const int tid = threadIdx.x;
    if (tid < Cn * Hn) ws[tid] = Wa[tid] * LOG2E;   // ws[c*Hn+h]
    if (tid < Hn) offs[tid] = ba[tid] * LOG2E;
    __syncthreads();

    const int b = b0 + (blockIdx.x >> 10);
    const int i = blockIdx.x & 1023;
    const float4* a4 = (const float4*)&adj[(size_t)(b * Nn + i) * Nn * Cn];
    const int j = tid * 4;
    float4 x0 = __ldcs(a4 + j);
    float4 x1 = __ldcs(a4 + j + 1);
    float4 x2 = __ldcs(a4 + j + 2);
    float4 x3 = __ldcs(a4 + j + 3);
#pragma unroll 1
    for (int h = 0; h < Hn; h++) {
        float w0 = ws[h], w1 = ws[8 + h], w2 = ws[16 + h], w3 = ws[24 + h];
        float o = offs[h];
        float v0 = o + x0.x * w0 + x0.y * w1 + x0.z * w2 + x0.w * w3;
        float v1 = o + x1.x * w0 + x1.y * w1 + x1.z * w2 + x1.w * w3;
        float v2 = o + x2.x * w0 + x2.y * w1 + x2.z * w2 + x2.w * w3;
        float v3 = o + x3.x * w0 + x3.y * w1 + x3.z * w2 + x3.w * w3;
        uint32_t pk = (uint32_t)pk_e4m3(v1, v0) | ((uint32_t)pk_e4m3(v3, v2) << 16);
        __stcs((uint32_t*)(g_bias8 + ((size_t)((b * Hn + h) * Nn + i)) * Nn) + tid, pk);
    }
}

// ============================================================================
// fp16 tensor-core flash attention, cp.async double-buffered; fp8 bias.
// Per buffer (u32): K@0 (1280), V^T@1280 (1152), bias8@2432 (128x20=2560) = 4992.
// Bias row pitch = 20 words (80 B) -> every cp.async dst 16B-aligned.
// ============================================================================
#define ABUF_W 4992
#define K_W 0
#define V_W 1280
#define BIAS_W 2432
#define ATTN_SMEM_BYTES (2 * ABUF_W * 4)

__global__ __launch_bounds__(256)
void attn_tc(int b0)
{
    extern __shared__ __align__(16) uint32_t S[];
    const uint32_t sb = smem_u32(S);
    const int tid = threadIdx.x;
    const int w = tid >> 5, lane = tid & 31;
    const int g = lane >> 2, t = lane & 3;
    const int i0 = blockIdx.x * 128;
    const int bh = (b0 + blockIdx.z) * Hn + blockIdx.y;

    const uint32_t* q32 = (const uint32_t*)g_qh;
    const int rowA = bh * Nn + i0 + w * 16 + g;
    const int rowB = rowA + 8;
    uint32_t aQ[2][4];
#pragma unroll
    for (int kt = 0; kt < 2; kt++) {
        aQ[kt][0] = q32[rowA * 16 + kt * 8 + t];
        aQ[kt][1] = q32[rowB * 16 + kt * 8 + t];
        aQ[kt][2] = q32[rowA * 16 + kt * 8 + 4 + t];
        aQ[kt][3] = q32[rowB * 16 + kt * 8 + 4 + t];
    }

    float O[4][4] = {};
    float lA = 0.f, lB = 0.f;

    const uint4* k4p = (const uint4*)g_kh;
    const uint4* v4p = (const uint4*)g_vth;
    const uint4* b84 = (const uint4*)g_bias8;

    const int k_row = tid >> 2, k_c = tid & 3;
    const int v_d = tid >> 3, v_c = tid & 7;

    auto stage = [&](int jt, int bb) {
        const int j0 = jt * 64;
        CP_A16(sb + (bb + K_W + k_row * 20 + k_c * 4) * 4,
               k4p + (bh * Nn + j0 + k_row) * 4 + k_c);
        CP_A16(sb + (bb + V_W + v_d * 36 + v_c * 4) * 4,
               v4p + (bh * Dn + v_d) * 128 + jt * 8 + v_c);
        // bias8: 128 rows x 4 uint4 (64 B/row), pitch 20 words (80 B)
#pragma unroll
        for (int r = 0; r < 2; r++) {
            int idx = tid + r * 256;
            int row = idx >> 2, c = idx & 3;
            CP_A16(sb + (bb + BIAS_W + row * 20 + c * 4) * 4,
                   b84 + ((size_t)(bh * Nn) + i0 + row) * 64 + jt * 4 + c);
        }
        CP_COMMIT();
    };

    stage(0, 0);
    for (int jt = 0; jt < 16; jt++) {
        const int bb = (jt & 1) * ABUF_W;
        if (jt + 1 < 16) {
            stage(jt + 1, ((jt + 1) & 1) * ABUF_W);
            CP_WAIT1();
        } else {
            CP_WAIT0();
        }
        __syncthreads();

        // ---- QK^T ----
        float c_[8][4] = {};
#pragma unroll
        for (int nt = 0; nt < 8; nt++) {
#pragma unroll
            for (int kt = 0; kt < 2; kt++) {
                int kw = bb + K_W + (nt * 8 + g) * 20 + kt * 8 + t;
                MMAH(c_[nt], aQ[kt], S[kw], S[kw + 4]);
            }
        }
        // ---- + bias from smem (fp8 -> half2) ----
        const uint32_t biA = sb + (bb + BIAS_W + (w * 16 + g) * 20) * 4;
        const uint32_t biB = biA + 8 * 20 * 4;
#pragma unroll
        for (int nt = 0; nt < 8; nt++) {
            uint16_t u0, u1;
            asm volatile("ld.shared.u16 %0, [%1];" : "=h"(u0) : "r"(biA + nt * 8 + 2 * t));
            asm volatile("ld.shared.u16 %0, [%1];" : "=h"(u1) : "r"(biB + nt * 8 + 2 * t));
            uint32_t hb0, hb1;
            asm volatile("cvt.rn.f16x2.e4m3x2 %0, %1;" : "=r"(hb0) : "h"(u0));
            asm volatile("cvt.rn.f16x2.e4m3x2 %0, %1;" : "=r"(hb1) : "h"(u1));
            __half2 h0 = *(__half2*)&hb0;
            __half2 h1 = *(__half2*)&hb1;
            c_[nt][0] += __low2float(h0);
            c_[nt][1] += __high2float(h0);
            c_[nt][2] += __low2float(h1);
            c_[nt][3] += __high2float(h1);
        }
        // ---- P = exp2(s) ----
        uint32_t PH[8], PH2[8];
#pragma unroll
        for (int nt = 0; nt < 8; nt++) {
            float p0 = ex2(c_[nt][0]), p1 = ex2(c_[nt][1]);
            float p2 = ex2(c_[nt][2]), p3 = ex2(c_[nt][3]);
            lA += p0 + p1;
            lB += p2 + p3;
            PH[nt]  = bitsh2(__floats2half2_rn(p0, p1));
            PH2[nt] = bitsh2(__floats2half2_rn(p2, p3));
        }
        // ---- PV ----
#pragma unroll
        for (int dnt = 0; dnt < 4; dnt++) {
#pragma unroll
            for (int u = 0; u < 4; u++) {
                int vw = bb + V_W + (dnt * 8 + g) * 36 + u * 8 + t;
                uint32_t aP[4] = {PH[2 * u], PH2[2 * u], PH[2 * u + 1], PH2[2 * u + 1]};
                MMAH(O[dnt], aP, S[vw], S[vw + 4]);
            }
        }
        __syncthreads();
    }

    lA += __shfl_xor_sync(0xffffffffu, lA, 1);
    lA += __shfl_xor_sync(0xffffffffu, lA, 2);
    lB += __shfl_xor_sync(0xffffffffu, lB, 1);
    lB += __shfl_xor_sync(0xffffffffu, lB, 2);
    const float iA = 1.f / lA, iB = 1.f / lB;

    const int b = bh >> 3, h = bh & 7;
    const int nA = rowA & (Nn - 1);
    const size_t baseA = ((size_t)b * Nn + nA) * En + h * Dn;
    const size_t baseB = baseA + 8 * En;
#pragma unroll
    for (int dnt = 0; dnt < 4; dnt++) {
        int dd = dnt * 8 + 2 * t;
        *(uint32_t*)&g_ch[baseA + dd] = bitsh2(__floats2half2_rn(O[dnt][0] * iA, O[dnt][1] * iA));
        *(uint32_t*)&g_ch[baseB + dd] = bitsh2(__floats2half2_rn(O[dnt][2] * iB, O[dnt][3] * iB));
    }
}

// ============================================================================
extern "C" void kernel_launch(void* const* d_in, const int* in_sizes, int n_in,
                              void* d_out, int out_size)
{
    const float* x   = (const float*)d_in[0];
    const float* adj = (const float*)d_in[1];
    const float* Wq  = (const float*)d_in[2];
    const float* bq  = (const float*)d_in[3];
    const float* Wk  = (const float*)d_in[4];
    const float* bk  = (const float*)d_in[5];
    const float* Wv  = (const float*)d_in[6];
    const float* bv  = (const float*)d_in[7];
    const float* Wo  = (const float*)d_in[8];
    const float* bo  = (const float*)d_in[9];
    const float* Wa  = (const float*)d_in[10];
    const float* ba  = (const float*)d_in[11];
    float* out = (float*)d_out;

    // one-time side-stream + events + smem attribute (host-side; no device alloc)
    static cudaStream_t s2 = nullptr;
    static cudaEvent_t evFork = nullptr, evB1 = nullptr, evB2 = nullptr;
    static cudaEvent_t evA1 = nullptr, evG1 = nullptr;
    if (s2 == nullptr) {
        cudaStreamCreateWithFlags(&s2, cudaStreamNonBlocking);
        cudaEventCreateWithFlags(&evFork, cudaEventDisableTiming);
        cudaEventCreateWithFlags(&evB1, cudaEventDisableTiming);
        cudaEventCreateWithFlags(&evB2, cudaEventDisableTiming);
        cudaEventCreateWithFlags(&evA1, cudaEventDisableTiming);
        cudaEventCreateWithFlags(&evG1, cudaEventDisableTiming);
        cudaFuncSetAttribute(attn_tc, cudaFuncAttributeMaxDynamicSharedMemorySize,
                             ATTN_SMEM_BYTES);
    }

    // fork: bias_pre halves on side stream
    cudaEventRecord(evFork, 0);
    cudaStreamWaitEvent(s2, evFork, 0);
    bias_pre<<<(Bn / 2) * Nn, 256, 0, s2>>>(adj, Wa, ba, 0);
    cudaEventRecord(evB1, s2);
    bias_pre<<<(Bn / 2) * Nn, 256, 0, s2>>>(adj, Wa, ba, 4);
    cudaEventRecord(evB2, s2);

    // main chain: converts + QKV GEMM (V transposed+converted in epilogue)
    convert_x<<<(Bn * Nn * En / 4) / 256, 256>>>(x);
    convert_wt<<<4 * 64, 256>>>(Wq, Wk, Wv, Wo);

    dim3 gq(En / 64, (Bn * Nn) / 128, 3);
    gemm_tc<0><<<gq, 256>>>(bq, bk, bv, nullptr, nullptr, 0);

    // attention half 1 (overlaps bias_pre half 2 on s2)
    cudaStreamWaitEvent(0, evB1, 0);
    dim3 ga(Nn / 128, Hn, Bn / 2);
    attn_tc<<<ga, 256, ATTN_SMEM_BYTES>>>(0);
    cudaEventRecord(evA1, 0);

    // out-proj half 1 on s2 (overlaps attention half 2)
    cudaStreamWaitEvent(s2, evA1, 0);
    dim3 go(En / 64, (Bn * Nn) / 128 / 2);
    gemm_tc<1><<<go, 256, 0, s2>>>(bo, bo, bo, x, out, 0);
    cudaEventRecord(evG1, s2);

    // attention half 2
    cudaStreamWaitEvent(0, evB2, 0);
    attn_tc<<<ga, 256, ATTN_SMEM_BYTES>>>(4);

    // out-proj half 2; join s2
    cudaStreamWaitEvent(0, evG1, 0);
    gemm_tc<1><<<go, 256>>>(bo, bo, bo, x, out, 32);
}

// round 14
// speedup vs baseline: 1.5115x; 1.5115x over previous
#include <cuda_runtime.h>
#include <cuda_bf16.h>
#include <cuda_fp16.h>
#include <cstdint>

#define Bn 8
#define Nn 1024
#define En 256
#define Hn 8
#define Dn 32
#define Cn 4

#define QSZ (Bn * Hn * Nn * Dn)            // 2M elems
__device__ __half g_xh[Bn * Nn * En];
__device__ __half g_qh[QSZ];
__device__ __half g_kh[QSZ];
__device__ __half g_vth[QSZ];              // [B,H,D,N]
__device__ __half g_ch[Bn * Nn * En];      // ctx row-major
__device__ __half g_wth[4 * En * En];      // W^T: q,k,v,o
__device__ uint8_t g_bias8[(size_t)Bn * Hn * Nn * Nn]; // 67MB e4m3, log2e-scaled

#define SCALEQ 0.25506807163967554f   // 1/sqrt(32) * log2e
#define LOG2E  1.4426950408889634f

__device__ __forceinline__ float ex2(float x) {
    float y;
    asm("ex2.approx.f32 %0, %1;" : "=f"(y) : "f"(x));
    return y;
}
__device__ __forceinline__ uint32_t bitsh2(__half2 v) {
    return *reinterpret_cast<uint32_t*>(&v);
}
__device__ __forceinline__ uint2 pack4h(float a, float b, float c, float d) {
    uint2 r;
    r.x = bitsh2(__floats2half2_rn(a, b));
    r.y = bitsh2(__floats2half2_rn(c, d));
    return r;
}
__device__ __forceinline__ uint32_t smem_u32(const void* p) {
    uint32_t a;
    asm("{ .reg .u64 t; cvta.to.shared.u64 t, %1; cvt.u32.u64 %0, t; }" : "=r"(a) : "l"(p));
    return a;
}
// pack two floats -> e4m3x2 (lo byte = second operand)
__device__ __forceinline__ uint16_t pk_e4m3(float hi, float lo) {
    uint16_t r;
    asm("cvt.rn.satfinite.e4m3x2.f32 %0, %1, %2;" : "=h"(r) : "f"(hi), "f"(lo));
    return r;
}

#define CP_A16(d, s) asm volatile("cp.async.cg.shared.global [%0], [%1], 16;" :: "r"(d), "l"(s) : "memory")
#define CP_COMMIT()  asm volatile("cp.async.commit_group;" ::: "memory")
#define CP_WAIT0()   asm volatile("cp.async.wait_group 0;" ::: "memory")
#define CP_WAIT1()   asm volatile("cp.async.wait_group 1;" ::: "memory")

#define MMAH(c, a, b0, b1)                                                    \
    asm volatile("mma.sync.aligned.m16n8k16.row.col.f32.f16.f16.f32 "         \
        "{%0,%1,%2,%3}, {%4,%5,%6,%7}, {%8,%9}, {%0,%1,%2,%3};"               \
        : "+f"((c)[0]), "+f"((c)[1]), "+f"((c)[2]), "+f"((c)[3])              \
        : "r"((a)[0]), "r"((a)[1]), "r"((a)[2]), "r"((a)[3]), "r"(b0), "r"(b1))

// ============================================================================
// convert x -> fp16
// ============================================================================
__global__ __launch_bounds__(256)
void convert_x(const float* __restrict__ x)
{
    int i = blockIdx.x * 256 + threadIdx.x;   // per float4
    float4 v = ((const float4*)x)[i];
    ((uint2*)g_xh)[i] = pack4h(v.x, v.y, v.z, v.w);
}

// ============================================================================
// convert W -> W^T fp16 (32x32 tiles)
// ============================================================================
__global__ __launch_bounds__(256)
void convert_wt(const float* __restrict__ W0, const float* __restrict__ W1,
                const float* __restrict__ W2, const float* __restrict__ W3)
{
    __shared__ float T[32][33];
    const int z = blockIdx.x >> 6;
    const int tile = blockIdx.x & 63;
    const int k0 = (tile >> 3) * 32;
    const int n0 = (tile & 7) * 32;
    const float* W = (z == 0) ? W0 : (z == 1) ? W1 : (z == 2) ? W2 : W3;
    const int tid = threadIdx.x;
    {
        int r = tid >> 3, c4 = tid & 7;
        float4 v = *(const float4*)&W[(k0 + r) * En + n0 + c4 * 4];
        T[r][c4 * 4 + 0] = v.x; T[r][c4 * 4 + 1] = v.y;
        T[r][c4 * 4 + 2] = v.z; T[r][c4 * 4 + 3] = v.w;
    }
    __syncthreads();
    {
        int r = tid >> 3, c4 = tid & 7;
        int off = z * En * En + (n0 + r) * En + k0 + c4 * 4;
        *(uint2*)&g_wth[off] = pack4h(T[c4 * 4 + 0][r], T[c4 * 4 + 1][r],
                                      T[c4 * 4 + 2][r], T[c4 * 4 + 3][r]);
    }
}

// ============================================================================
// fp16 tensor-core GEMM, cp.async double-buffered.
// MODE 0: QKV (z=blockIdx.z; epilogue -> fp16 Q(scaled)/K; V transposed+fp16
//          through smem restage -> g_vth [B,H,D,N])
// MODE 1: out-proj (A=g_ch, W slot 3; epilogue -> +bo +x -> out fp32)
// ============================================================================
#define GBUF_W 3840          // per buffer: A@0 (2560) + B@2560 (1280)
#define GB_OFF 2560

template <int MODE>
__global__ __launch_bounds__(256)
void gemm_tc(const float* __restrict__ bias0, const float* __restrict__ bias1,
             const float* __restrict__ bias2,
             const float* __restrict__ X, float* __restrict__ OutR)
{
    __shared__ __align__(16) uint32_t S[2 * GBUF_W];   // 30 KB
    const uint32_t sb = smem_u32(S);
    const int tid = threadIdx.x;
    const int w = tid >> 5, lane = tid & 31;
    const int g = lane >> 2, t = lane & 3;
    const int row0 = blockIdx.y * 128;
    const int col0 = blockIdx.x * 64;
    const int z = (MODE == 0) ? blockIdx.z : 3;

    const uint4* a4p = (const uint4*)((MODE == 0) ? g_xh : g_ch);
    const uint4* b4p = (const uint4*)(g_wth + z * En * En);

    float c_[8][4] = {};

    const int a_row = tid >> 1;          // 0..127
    const int a_c4 = (tid & 1) * 2;      // uint4 col 0/2
    const int b_row = tid >> 2;          // 0..63
    const int b_c4 = tid & 3;

    auto stage = [&](int kc, int bb) {
        size_t siA = (size_t)(row0 + a_row) * 32 + kc * 4 + a_c4;
        CP_A16(sb + (bb + a_row * 20 + a_c4 * 4) * 4, a4p + siA);
        CP_A16(sb + (bb + a_row * 20 + (a_c4 + 1) * 4) * 4, a4p + siA + 1);
        size_t siB = (size_t)(col0 + b_row) * 32 + kc * 4 + b_c4;
        CP_A16(sb + (bb + GB_OFF + b_row * 20 + b_c4 * 4) * 4, b4p + siB);
        CP_COMMIT();
    };

    stage(0, 0);
    for (int kc = 0; kc < 8; kc++) {
        const int bb = (kc & 1) * GBUF_W;
        if (kc + 1 < 8) {
            stage(kc + 1, ((kc + 1) & 1) * GBUF_W);
            CP_WAIT1();
        } else {
            CP_WAIT0();
        }
        __syncthreads();
#pragma unroll
        for (int kt = 0; kt < 2; kt++) {
            const int aw = bb + (w * 16 + g) * 20 + kt * 8 + t;
            uint32_t a[4];
            a[0] = S[aw];       a[1] = S[aw + 160];
            a[2] = S[aw + 4];   a[3] = S[aw + 164];
#pragma unroll
            for (int nt = 0; nt < 8; nt++) {
                const int kw = bb + GB_OFF + (nt * 8 + g) * 20 + kt * 8 + t;
                MMAH(c_[nt], a, S[kw], S[kw + 4]);
            }
        }
        __syncthreads();
    }

    const int m = row0 + w * 16 + g;
    if (MODE == 0) {
        const float* bias = (z == 0) ? bias0 : (z == 1) ? bias1 : bias2;
        const int b = row0 >> 10, n0 = row0 & 1023;
        const int n = m & 1023;
        if (z < 2) {
#pragma unroll
            for (int nt = 0; nt < 8; nt++) {
                int col = col0 + nt * 8 + 2 * t;
                float bz0 = bias[col], bz1 = bias[col + 1];
                float v0 = c_[nt][0] + bz0, v1 = c_[nt][1] + bz1;
                float v2 = c_[nt][2] + bz0, v3 = c_[nt][3] + bz1;
                int h = col >> 5, dd = col & 31;
                size_t oA = ((size_t)(b * Hn + h) * Nn + n) * Dn + dd;
                size_t oB = oA + 8 * Dn;
                if (z == 0) {
                    v0 *= SCALEQ; v1 *= SCALEQ; v2 *= SCALEQ; v3 *= SCALEQ;
                    *(uint32_t*)&g_qh[oA] = bitsh2(__floats2half2_rn(v0, v1));
                    *(uint32_t*)&g_qh[oB] = bitsh2(__floats2half2_rn(v2, v3));
                } else {
                    *(uint32_t*)&g_kh[oA] = bitsh2(__floats2half2_rn(v0, v1));
                    *(uint32_t*)&g_kh[oB] = bitsh2(__floats2half2_rn(v2, v3));
                }
            }
        } else {
            // V: transpose through smem (k-loop done; S reusable) -> g_vth [B,H,D,N]
            __half* S2 = (__half*)S;
            const int lr = w * 16 + g;
#pragma unroll
            for (int nt = 0; nt < 8; nt++) {
                int lc = nt * 8 + 2 * t;
                int col = col0 + lc;
                float bz0 = bias[col], bz1 = bias[col + 1];
                S2[lc * 136 + lr]           = __float2half_rn(c_[nt][0] + bz0);
                S2[(lc + 1) * 136 + lr]     = __float2half_rn(c_[nt][1] + bz1);
                S2[lc * 136 + lr + 8]       = __float2half_rn(c_[nt][2] + bz0);
                S2[(lc + 1) * 136 + lr + 8] = __float2half_rn(c_[nt][3] + bz1);
            }
            __syncthreads();
            const int colx = tid >> 2, seg = tid & 3;
            const int gc = col0 + colx;
            const int h = gc >> 5, dd = gc & 31;
            size_t dst = ((size_t)(b * Hn + h) * Dn + dd) * Nn + n0 + seg * 32;
            const uint4* sp = (const uint4*)&S2[colx * 136 + seg * 32];
            uint4* dp = (uint4*)&g_vth[dst];
            dp[0] = sp[0]; dp[1] = sp[1]; dp[2] = sp[2]; dp[3] = sp[3];
        }
    } else {
#pragma unroll
        for (int nt = 0; nt < 8; nt++) {
            int col = col0 + nt * 8 + 2 * t;
            float bz0 = bias0[col], bz1 = bias0[col + 1];
            float2 xA = *(const float2*)&X[(size_t)m * En + col];
            float2 xB = *(const float2*)&X[(size_t)(m + 8) * En + col];
            float2 oA = {c_[nt][0] + bz0 + xA.x, c_[nt][1] + bz1 + xA.y};
            float2 oB = {c_[nt][2] + bz0 + xB.x, c_[nt][3] + bz1 + xB.y};
            *(float2*)&OutR[(size_t)m * En + col] = oA;
            *(float2*)&OutR[(size_t)(m + 8) * En + col] = oB;
        }
    }
}

// ============================================================================
// bias precompute -> e4m3 fp8, log2e-scaled.  Half-batch per launch (b0).
// R11 load pattern (known-good coalescing); only the store dtype changed.
// ============================================================================
__global__ __launch_bounds__(256)
void bias_pre(const float* __restrict__ adj, const float* __restrict__ Wa,
              const float* __restrict__ ba, int b0)
{
    __shared__ float ws[Cn * Hn];
    __shared__ float offs[Hn];
    const int tid = threadIdx.x;
    if (tid < Cn * Hn) ws[tid] = Wa[tid] * LOG2E;   // ws[c*Hn+h]
    if (tid < Hn) offs[tid] = ba[tid] * LOG2E;
    __syncthreads();

    const int b = b0 + (blockIdx.x >> 10);
    const int i = blockIdx.x & 1023;
    const float4* a4 = (const float4*)&adj[(size_t)(b * Nn + i) * Nn * Cn];
#pragma unroll
    for (int r = 0; r < 2; r++) {
        int j = (tid + r * 256) * 2;
        float4 x0 = __ldcs(a4 + j);
        float4 x1 = __ldcs(a4 + j + 1);
#pragma unroll 1
        for (int h = 0; h < Hn; h++) {
            float w0 = ws[h], w1 = ws[8 + h], w2 = ws[16 + h], w3 = ws[24 + h];
            float o = offs[h];
            float v0 = o + x0.x * w0 + x0.y * w1 + x0.z * w2 + x0.w * w3;
            float v1 = o + x1.x * w0 + x1.y * w1 + x1.z * w2 + x1.w * w3;
            __stcs((uint16_t*)(g_bias8 + ((size_t)((b * Hn + h) * Nn + i)) * Nn + j),
                   pk_e4m3(v1, v0));
        }
    }
}

// ============================================================================
// fp16 tensor-core flash attention, cp.async double-buffered; fp8 bias.
// Per buffer (u32): K@0 (1280), V^T@1280 (1152), bias8@2432 (128x20=2560) = 4992.
// Bias row pitch = 20 words (80 B) -> every cp.async dst 16B-aligned.
// Half-batch per launch (b0) so it overlaps the other half's bias_pre.
// ============================================================================
#define ABUF_W 4992
#define K_W 0
#define V_W 1280
#define BIAS_W 2432
#define ATTN_SMEM_BYTES (2 * ABUF_W * 4)

__global__ __launch_bounds__(256)
void attn_tc(int b0)
{
    extern __shared__ __align__(16) uint32_t S[];
    const uint32_t sb = smem_u32(S);
    const int tid = threadIdx.x;
    const int w = tid >> 5, lane = tid & 31;
    const int g = lane >> 2, t = lane & 3;
    const int i0 = blockIdx.x * 128;
    const int bh = (b0 + blockIdx.z) * Hn + blockIdx.y;

    const uint32_t* q32 = (const uint32_t*)g_qh;
    const int rowA = bh * Nn + i0 + w * 16 + g;
    const int rowB = rowA + 8;
    uint32_t aQ[2][4];
#pragma unroll
    for (int kt = 0; kt < 2; kt++) {
        aQ[kt][0] = q32[rowA * 16 + kt * 8 + t];
        aQ[kt][1] = q32[rowB * 16 + kt * 8 + t];
        aQ[kt][2] = q32[rowA * 16 + kt * 8 + 4 + t];
        aQ[kt][3] = q32[rowB * 16 + kt * 8 + 4 + t];
    }

    float O[4][4] = {};
    float lA = 0.f, lB = 0.f;

    const uint4* k4p = (const uint4*)g_kh;
    const uint4* v4p = (const uint4*)g_vth;
    const uint4* b84 = (const uint4*)g_bias8;

    const int k_row = tid >> 2, k_c = tid & 3;
    const int v_d = tid >> 3, v_c = tid & 7;

    auto stage = [&](int jt, int bb) {
        const int j0 = jt * 64;
        CP_A16(sb + (bb + K_W + k_row * 20 + k_c * 4) * 4,
               k4p + (bh * Nn + j0 + k_row) * 4 + k_c);
        CP_A16(sb + (bb + V_W + v_d * 36 + v_c * 4) * 4,
               v4p + (bh * Dn + v_d) * 128 + jt * 8 + v_c);
        // bias8: 128 rows x 4 uint4 (64 B/row), smem pitch 20 words (80 B)
#pragma unroll
        for (int r = 0; r < 2; r++) {
            int idx = tid + r * 256;
            int row = idx >> 2, c = idx & 3;
            CP_A16(sb + (bb + BIAS_W + row * 20 + c * 4) * 4,
                   b84 + ((size_t)(bh * Nn) + i0 + row) * 64 + jt * 4 + c);
        }
        CP_COMMIT();
    };

    stage(0, 0);
    for (int jt = 0; jt < 16; jt++) {
        const int bb = (jt & 1) * ABUF_W;
        if (jt + 1 < 16) {
            stage(jt + 1, ((jt + 1) & 1) * ABUF_W);
            CP_WAIT1();
        } else {
            CP_WAIT0();
        }
        __syncthreads();

        // ---- QK^T ----
        float c_[8][4] = {};
#pragma unroll
        for (int nt = 0; nt < 8; nt++) {
#pragma unroll
            for (int kt = 0; kt < 2; kt++) {
                int kw = bb + K_W + (nt * 8 + g) * 20 + kt * 8 + t;
                MMAH(c_[nt], aQ[kt], S[kw], S[kw + 4]);
            }
        }
        // ---- + bias from smem (fp8 -> half2) ----
        const uint32_t biA = sb + (bb + BIAS_W + (w * 16 + g) * 20) * 4;
        const uint32_t biB = biA + 8 * 20 * 4;
#pragma unroll
        for (int nt = 0; nt < 8; nt++) {
            uint16_t u0, u1;
            asm volatile("ld.shared.u16 %0, [%1];" : "=h"(u0) : "r"(biA + nt * 8 + 2 * t));
            asm volatile("ld.shared.u16 %0, [%1];" : "=h"(u1) : "r"(biB + nt * 8 + 2 * t));
            uint32_t hb0, hb1;
            asm volatile("cvt.rn.f16x2.e4m3x2 %0, %1;" : "=r"(hb0) : "h"(u0));
            asm volatile("cvt.rn.f16x2.e4m3x2 %0, %1;" : "=r"(hb1) : "h"(u1));
            __half2 h0 = *(__half2*)&hb0;
            __half2 h1 = *(__half2*)&hb1;
            c_[nt][0] += __low2float(h0);
            c_[nt][1] += __high2float(h0);
            c_[nt][2] += __low2float(h1);
            c_[nt][3] += __high2float(h1);
        }
        // ---- P = exp2(s) ----
        uint32_t PH[8], PH2[8];
#pragma unroll
        for (int nt = 0; nt < 8; nt++) {
            float p0 = ex2(c_[nt][0]), p1 = ex2(c_[nt][1]);
            float p2 = ex2(c_[nt][2]), p3 = ex2(c_[nt][3]);
            lA += p0 + p1;
            lB += p2 + p3;
            PH[nt]  = bitsh2(__floats2half2_rn(p0, p1));
            PH2[nt] = bitsh2(__floats2half2_rn(p2, p3));
        }
        // ---- PV ----
#pragma unroll
        for (int dnt = 0; dnt < 4; dnt++) {
#pragma unroll
            for (int u = 0; u < 4; u++) {
                int vw = bb + V_W + (dnt * 8 + g) * 36 + u * 8 + t;
                uint32_t aP[4] = {PH[2 * u], PH2[2 * u], PH[2 * u + 1], PH2[2 * u + 1]};
                MMAH(O[dnt], aP, S[vw], S[vw + 4]);
            }
        }
        __syncthreads();
    }

    lA += __shfl_xor_sync(0xffffffffu, lA, 1);
    lA += __shfl_xor_sync(0xffffffffu, lA, 2);
    lB += __shfl_xor_sync(0xffffffffu, lB, 1);
    lB += __shfl_xor_sync(0xffffffffu, lB, 2);
    const float iA = 1.f / lA, iB = 1.f / lB;

    const int b = bh >> 3, h = bh & 7;
    const int nA = rowA & (Nn - 1);
    const size_t baseA = ((size_t)b * Nn + nA) * En + h * Dn;
    const size_t baseB = baseA + 8 * En;
#pragma unroll
    for (int dnt = 0; dnt < 4; dnt++) {
        int dd = dnt * 8 + 2 * t;
        *(uint32_t*)&g_ch[baseA + dd] = bitsh2(__floats2half2_rn(O[dnt][0] * iA, O[dnt][1] * iA));
        *(uint32_t*)&g_ch[baseB + dd] = bitsh2(__floats2half2_rn(O[dnt][2] * iB, O[dnt][3] * iB));
    }
}

// ============================================================================
extern "C" void kernel_launch(void* const* d_in, const int* in_sizes, int n_in,
                              void* d_out, int out_size)
{
    const float* x   = (const float*)d_in[0];
    const float* adj = (const float*)d_in[1];
    const float* Wq  = (const float*)d_in[2];
    const float* bq  = (const float*)d_in[3];
    const float* Wk  = (const float*)d_in[4];
    const float* bk  = (const float*)d_in[5];
    const float* Wv  = (const float*)d_in[6];
    const float* bv  = (const float*)d_in[7];
    const float* Wo  = (const float*)d_in[8];
    const float* bo  = (const float*)d_in[9];
    const float* Wa  = (const float*)d_in[10];
    const float* ba  = (const float*)d_in[11];
    float* out = (float*)d_out;

    // one-time side-stream + events + smem attribute (host-side; no device alloc)
    static cudaStream_t s2 = nullptr;
    static cudaEvent_t evFork = nullptr, evB1 = nullptr, evB2 = nullptr;
    if (s2 == nullptr) {
        cudaStreamCreateWithFlags(&s2, cudaStreamNonBlocking);
        cudaEventCreateWithFlags(&evFork, cudaEventDisableTiming);
        cudaEventCreateWithFlags(&evB1, cudaEventDisableTiming);
        cudaEventCreateWithFlags(&evB2, cudaEventDisableTiming);
        cudaFuncSetAttribute(attn_tc, cudaFuncAttributeMaxDynamicSharedMemorySize,
                             ATTN_SMEM_BYTES);
    }

    // fork: bias_pre in two batch halves on side stream
    cudaEventRecord(evFork, 0);
    cudaStreamWaitEvent(s2, evFork, 0);
    bias_pre<<<(Bn / 2) * Nn, 256, 0, s2>>>(adj, Wa, ba, 0);
    cudaEventRecord(evB1, s2);
    bias_pre<<<(Bn / 2) * Nn, 256, 0, s2>>>(adj, Wa, ba, 4);
    cudaEventRecord(evB2, s2);

    // main chain: converts + QKV GEMM (V transposed+converted in epilogue)
    convert_x<<<(Bn * Nn * En / 4) / 256, 256>>>(x);
    convert_wt<<<4 * 64, 256>>>(Wq, Wk, Wv, Wo);

    dim3 gq(En / 64, (Bn * Nn) / 128, 3);
    gemm_tc<0><<<gq, 256>>>(bq, bk, bv, nullptr, nullptr);

    // attention half 1 (overlaps bias_pre half 2 on s2)
    cudaStreamWaitEvent(0, evB1, 0);
    dim3 ga(Nn / 128, Hn, Bn / 2);
    attn_tc<<<ga, 256, ATTN_SMEM_BYTES>>>(0);

    // attention half 2
    cudaStreamWaitEvent(0, evB2, 0);
    attn_tc<<<ga, 256, ATTN_SMEM_BYTES>>>(4);

    // output projection + residual
    dim3 go(En / 64, (Bn * Nn) / 128);
    gemm_tc<1><<<go, 256>>>(bo, bo, bo, x, out);
}

// round 15
// speedup vs baseline: 1.6344x; 1.0813x over previous
#include <cuda_runtime.h>
#include <cuda_bf16.h>
#include <cuda_fp16.h>
#include <cstdint>

#define Bn 8
#define Nn 1024
#define En 256
#define Hn 8
#define Dn 32
#define Cn 4

#define QSZ (Bn * Hn * Nn * Dn)            // 2M elems
__device__ __half g_xh[Bn * Nn * En];
__device__ __half g_qh[QSZ];
__device__ __half g_kh[QSZ];
__device__ __half g_vth[QSZ];              // [B,H,D,N]
__device__ __half g_ch[Bn * Nn * En];      // ctx row-major
__device__ __half g_wth[4 * En * En];      // W^T: q,k,v,o
__device__ uint8_t g_bias8[(size_t)Bn * Hn * Nn * Nn]; // 67MB e4m3, log2e-scaled

#define SCALEQ 0.25506807163967554f   // 1/sqrt(32) * log2e
#define LOG2E  1.4426950408889634f

__device__ __forceinline__ uint32_t bitsh2(__half2 v) {
    return *reinterpret_cast<uint32_t*>(&v);
}
__device__ __forceinline__ uint2 pack4h(float a, float b, float c, float d) {
    uint2 r;
    r.x = bitsh2(__floats2half2_rn(a, b));
    r.y = bitsh2(__floats2half2_rn(c, d));
    return r;
}
__device__ __forceinline__ uint32_t smem_u32(const void* p) {
    uint32_t a;
    asm("{ .reg .u64 t; cvta.to.shared.u64 t, %1; cvt.u32.u64 %0, t; }" : "=r"(a) : "l"(p));
    return a;
}
// pack two floats -> e4m3x2 (lo byte = second operand)
__device__ __forceinline__ uint16_t pk_e4m3(float hi, float lo) {
    uint16_t r;
    asm("cvt.rn.satfinite.e4m3x2.f32 %0, %1, %2;" : "=h"(r) : "f"(hi), "f"(lo));
    return r;
}

#define CP_A16(d, s) asm volatile("cp.async.cg.shared.global [%0], [%1], 16;" :: "r"(d), "l"(s) : "memory")
#define CP_COMMIT()  asm volatile("cp.async.commit_group;" ::: "memory")
#define CP_WAIT0()   asm volatile("cp.async.wait_group 0;" ::: "memory")
#define CP_WAIT1()   asm volatile("cp.async.wait_group 1;" ::: "memory")

#define MMAH(c, a, b0, b1)                                                    \
    asm volatile("mma.sync.aligned.m16n8k16.row.col.f32.f16.f16.f32 "         \
        "{%0,%1,%2,%3}, {%4,%5,%6,%7}, {%8,%9}, {%0,%1,%2,%3};"               \
        : "+f"((c)[0]), "+f"((c)[1]), "+f"((c)[2]), "+f"((c)[3])              \
        : "r"((a)[0]), "r"((a)[1]), "r"((a)[2]), "r"((a)[3]), "r"(b0), "r"(b1))

// ============================================================================
// convert x -> fp16
// ============================================================================
__global__ __launch_bounds__(256)
void convert_x(const float* __restrict__ x)
{
    int i = blockIdx.x * 256 + threadIdx.x;   // per float4
    float4 v = ((const float4*)x)[i];
    ((uint2*)g_xh)[i] = pack4h(v.x, v.y, v.z, v.w);
}

// ============================================================================
// convert W -> W^T fp16 (32x32 tiles)
// ============================================================================
__global__ __launch_bounds__(256)
void convert_wt(const float* __restrict__ W0, const float* __restrict__ W1,
                const float* __restrict__ W2, const float* __restrict__ W3)
{
    __shared__ float T[32][33];
    const int z = blockIdx.x >> 6;
    const int tile = blockIdx.x & 63;
    const int k0 = (tile >> 3) * 32;
    const int n0 = (tile & 7) * 32;
    const float* W = (z == 0) ? W0 : (z == 1) ? W1 : (z == 2) ? W2 : W3;
    const int tid = threadIdx.x;
    {
        int r = tid >> 3, c4 = tid & 7;
        float4 v = *(const float4*)&W[(k0 + r) * En + n0 + c4 * 4];
        T[r][c4 * 4 + 0] = v.x; T[r][c4 * 4 + 1] = v.y;
        T[r][c4 * 4 + 2] = v.z; T[r][c4 * 4 + 3] = v.w;
    }
    __syncthreads();
    {
        int r = tid >> 3, c4 = tid & 7;
        int off = z * En * En + (n0 + r) * En + k0 + c4 * 4;
        *(uint2*)&g_wth[off] = pack4h(T[c4 * 4 + 0][r], T[c4 * 4 + 1][r],
                                      T[c4 * 4 + 2][r], T[c4 * 4 + 3][r]);
    }
}

// ============================================================================
// fp16 tensor-core GEMM, cp.async 3-stage pipelined (one sync per chunk).
// MODE 0: QKV (z=blockIdx.z; epilogue -> fp16 Q(scaled)/K; V transposed+fp16
//          through smem restage -> g_vth [B,H,D,N])
// MODE 1: out-proj (A=g_ch, W slot 3; epilogue -> +bo +x -> out fp32)
// ============================================================================
#define GBUF_W 3840          // per buffer: A@0 (2560) + B@2560 (1280)
#define GB_OFF 2560

template <int MODE>
__global__ __launch_bounds__(256)
void gemm_tc(const float* __restrict__ bias0, const float* __restrict__ bias1,
             const float* __restrict__ bias2,
             const float* __restrict__ X, float* __restrict__ OutR)
{
    __shared__ __align__(16) uint32_t S[3 * GBUF_W];   // 45 KB
    const uint32_t sb = smem_u32(S);
    const int tid = threadIdx.x;
    const int w = tid >> 5, lane = tid & 31;
    const int g = lane >> 2, t = lane & 3;
    const int row0 = blockIdx.y * 128;
    const int col0 = blockIdx.x * 64;
    const int z = (MODE == 0) ? blockIdx.z : 3;

    const uint4* a4p = (const uint4*)((MODE == 0) ? g_xh : g_ch);
    const uint4* b4p = (const uint4*)(g_wth + z * En * En);

    float c_[8][4] = {};

    const int a_row = tid >> 1;          // 0..127
    const int a_c4 = (tid & 1) * 2;      // uint4 col 0/2
    const int b_row = tid >> 2;          // 0..63
    const int b_c4 = tid & 3;

    auto stage = [&](int kc, int bb) {
        size_t siA = (size_t)(row0 + a_row) * 32 + kc * 4 + a_c4;
        CP_A16(sb + (bb + a_row * 20 + a_c4 * 4) * 4, a4p + siA);
        CP_A16(sb + (bb + a_row * 20 + (a_c4 + 1) * 4) * 4, a4p + siA + 1);
        size_t siB = (size_t)(col0 + b_row) * 32 + kc * 4 + b_c4;
        CP_A16(sb + (bb + GB_OFF + b_row * 20 + b_c4 * 4) * 4, b4p + siB);
        CP_COMMIT();
    };

    stage(0, 0);
    stage(1, GBUF_W);
    for (int kc = 0; kc < 8; kc++) {
        if (kc + 1 < 8) CP_WAIT1(); else CP_WAIT0();
        __syncthreads();
        if (kc + 2 < 8) stage(kc + 2, ((kc + 2) % 3) * GBUF_W);
        const int bb = (kc % 3) * GBUF_W;
#pragma unroll
        for (int kt = 0; kt < 2; kt++) {
            const int aw = bb + (w * 16 + g) * 20 + kt * 8 + t;
            uint32_t a[4];
            a[0] = S[aw];       a[1] = S[aw + 160];
            a[2] = S[aw + 4];   a[3] = S[aw + 164];
#pragma unroll
            for (int nt = 0; nt < 8; nt++) {
                const int kw = bb + GB_OFF + (nt * 8 + g) * 20 + kt * 8 + t;
                MMAH(c_[nt], a, S[kw], S[kw + 4]);
            }
        }
    }
    __syncthreads();

    const int m = row0 + w * 16 + g;
    if (MODE == 0) {
        const float* bias = (z == 0) ? bias0 : (z == 1) ? bias1 : bias2;
        const int b = row0 >> 10, n0 = row0 & 1023;
        const int n = m & 1023;
        if (z < 2) {
#pragma unroll
            for (int nt = 0; nt < 8; nt++) {
                int col = col0 + nt * 8 + 2 * t;
                float bz0 = bias[col], bz1 = bias[col + 1];
                float v0 = c_[nt][0] + bz0, v1 = c_[nt][1] + bz1;
                float v2 = c_[nt][2] + bz0, v3 = c_[nt][3] + bz1;
                int h = col >> 5, dd = col & 31;
                size_t oA = ((size_t)(b * Hn + h) * Nn + n) * Dn + dd;
                size_t oB = oA + 8 * Dn;
                if (z == 0) {
                    v0 *= SCALEQ; v1 *= SCALEQ; v2 *= SCALEQ; v3 *= SCALEQ;
                    *(uint32_t*)&g_qh[oA] = bitsh2(__floats2half2_rn(v0, v1));
                    *(uint32_t*)&g_qh[oB] = bitsh2(__floats2half2_rn(v2, v3));
                } else {
                    *(uint32_t*)&g_kh[oA] = bitsh2(__floats2half2_rn(v0, v1));
                    *(uint32_t*)&g_kh[oB] = bitsh2(__floats2half2_rn(v2, v3));
                }
            }
        } else {
            // V: transpose through smem (k-loop done; S reusable) -> g_vth [B,H,D,N]
            __half* S2 = (__half*)S;
            const int lr = w * 16 + g;
#pragma unroll
            for (int nt = 0; nt < 8; nt++) {
                int lc = nt * 8 + 2 * t;
                int col = col0 + lc;
                float bz0 = bias[col], bz1 = bias[col + 1];
                S2[lc * 136 + lr]           = __float2half_rn(c_[nt][0] + bz0);
                S2[(lc + 1) * 136 + lr]     = __float2half_rn(c_[nt][1] + bz1);
                S2[lc * 136 + lr + 8]       = __float2half_rn(c_[nt][2] + bz0);
                S2[(lc + 1) * 136 + lr + 8] = __float2half_rn(c_[nt][3] + bz1);
            }
            __syncthreads();
            const int colx = tid >> 2, seg = tid & 3;
            const int gc = col0 + colx;
            const int h = gc >> 5, dd = gc & 31;
            size_t dst = ((size_t)(b * Hn + h) * Dn + dd) * Nn + n0 + seg * 32;
            const uint4* sp = (const uint4*)&S2[colx * 136 + seg * 32];
            uint4* dp = (uint4*)&g_vth[dst];
            dp[0] = sp[0]; dp[1] = sp[1]; dp[2] = sp[2]; dp[3] = sp[3];
        }
    } else {
#pragma unroll
        for (int nt = 0; nt < 8; nt++) {
            int col = col0 + nt * 8 + 2 * t;
            float bz0 = bias0[col], bz1 = bias0[col + 1];
            float2 xA = *(const float2*)&X[(size_t)m * En + col];
            float2 xB = *(const float2*)&X[(size_t)(m + 8) * En + col];
            float2 oA = {c_[nt][0] + bz0 + xA.x, c_[nt][1] + bz1 + xA.y};
            float2 oB = {c_[nt][2] + bz0 + xB.x, c_[nt][3] + bz1 + xB.y};
            *(float2*)&OutR[(size_t)m * En + col] = oA;
            *(float2*)&OutR[(size_t)(m + 8) * En + col] = oB;
        }
    }
}

// ============================================================================
// bias precompute -> e4m3 fp8, log2e-scaled.  Half-batch per launch (b0).
// ============================================================================
__global__ __launch_bounds__(256)
void bias_pre(const float* __restrict__ adj, const float* __restrict__ Wa,
              const float* __restrict__ ba, int b0)
{
    __shared__ float ws[Cn * Hn];
    __shared__ float offs[Hn];
    const int tid = threadIdx.x;
    if (tid < Cn * Hn) ws[tid] = Wa[tid] * LOG2E;   // ws[c*Hn+h]
    if (tid < Hn) offs[tid] = ba[tid] * LOG2E;
    __syncthreads();

    const int b = b0 + (blockIdx.x >> 10);
    const int i = blockIdx.x & 1023;
    const float4* a4 = (const float4*)&adj[(size_t)(b * Nn + i) * Nn * Cn];
#pragma unroll
    for (int r = 0; r < 2; r++) {
        int j = (tid + r * 256) * 2;
        float4 x0 = __ldcs(a4 + j);
        float4 x1 = __ldcs(a4 + j + 1);
#pragma unroll 1
        for (int h = 0; h < Hn; h++) {
            float w0 = ws[h], w1 = ws[8 + h], w2 = ws[16 + h], w3 = ws[24 + h];
            float o = offs[h];
            float v0 = o + x0.x * w0 + x0.y * w1 + x0.z * w2 + x0.w * w3;
            float v1 = o + x1.x * w0 + x1.y * w1 + x1.z * w2 + x1.w * w3;
            __stcs((uint16_t*)(g_bias8 + ((size_t)((b * Hn + h) * Nn + i)) * Nn + j),
                   pk_e4m3(v1, v0));
        }
    }
}

// ============================================================================
// fp16 tensor-core flash attention; fp8 bias; half2 softmax; l via ones-row MMA.
// Per buffer (u32): K@0 (1280), V^T@1280 (40 rows x 36 = 1440; rows 32..39 are
// ones/zeros for the l-reduction), bias8@2720 (128x20=2560) = 5280.
// ============================================================================
#define ABUF_W 5280
#define K_W 0
#define V_W 1280
#define BIAS_W 2720
#define ATTN_SMEM_BYTES (2 * ABUF_W * 4)

__global__ __launch_bounds__(256)
void attn_tc(int b0)
{
    extern __shared__ __align__(16) uint32_t S[];
    const uint32_t sb = smem_u32(S);
    const int tid = threadIdx.x;
    const int w = tid >> 5, lane = tid & 31;
    const int g = lane >> 2, t = lane & 3;
    const int i0 = blockIdx.x * 128;
    const int bh = (b0 + blockIdx.z) * Hn + blockIdx.y;

    const uint32_t* q32 = (const uint32_t*)g_qh;
    const int rowA = bh * Nn + i0 + w * 16 + g;
    const int rowB = rowA + 8;
    uint32_t aQ[2][4];
#pragma unroll
    for (int kt = 0; kt < 2; kt++) {
        aQ[kt][0] = q32[rowA * 16 + kt * 8 + t];
        aQ[kt][1] = q32[rowB * 16 + kt * 8 + t];
        aQ[kt][2] = q32[rowA * 16 + kt * 8 + 4 + t];
        aQ[kt][3] = q32[rowB * 16 + kt * 8 + 4 + t];
    }

    float O[4][4] = {};
    float O5[4] = {};          // l accumulator (ones column); lA at [0], lB at [2] for t==0

    const uint4* k4p = (const uint4*)g_kh;
    const uint4* v4p = (const uint4*)g_vth;
    const uint4* b84 = (const uint4*)g_bias8;

    const int k_row = tid >> 2, k_c = tid & 3;
    const int v_d = tid >> 3, v_c = tid & 7;

    // init ones/zero rows 32..39 of V region in both buffers (cp.async never
    // touches them); first loop-iteration __syncthreads() publishes them.
#pragma unroll
    for (int bbi = 0; bbi < 2; bbi++) {
        int base = bbi * ABUF_W + V_W + 32 * 36;
        for (int idx = tid; idx < 8 * 36; idx += 256) {
            int rrow = idx / 36;
            S[base + idx] = (rrow == 0) ? 0x3C003C00u : 0u;   // half2(1,1) : 0
        }
    }

    auto stage = [&](int jt, int bb) {
        const int j0 = jt * 64;
        CP_A16(sb + (bb + K_W + k_row * 20 + k_c * 4) * 4,
               k4p + (bh * Nn + j0 + k_row) * 4 + k_c);
        CP_A16(sb + (bb + V_W + v_d * 36 + v_c * 4) * 4,
               v4p + (bh * Dn + v_d) * 128 + jt * 8 + v_c);
        // bias8: 128 rows x 4 uint4 (64 B/row), smem pitch 20 words (80 B)
#pragma unroll
        for (int r = 0; r < 2; r++) {
            int idx = tid + r * 256;
            int row = idx >> 2, c = idx & 3;
            CP_A16(sb + (bb + BIAS_W + row * 20 + c * 4) * 4,
                   b84 + ((size_t)(bh * Nn) + i0 + row) * 64 + jt * 4 + c);
        }
        CP_COMMIT();
    };

    stage(0, 0);
    for (int jt = 0; jt < 16; jt++) {
        const int bb = (jt & 1) * ABUF_W;
        if (jt + 1 < 16) {
            stage(jt + 1, ((jt + 1) & 1) * ABUF_W);
            CP_WAIT1();
        } else {
            CP_WAIT0();
        }
        __syncthreads();

        // ---- QK^T ----
        float c_[8][4] = {};
#pragma unroll
        for (int nt = 0; nt < 8; nt++) {
#pragma unroll
            for (int kt = 0; kt < 2; kt++) {
                int kw = bb + K_W + (nt * 8 + g) * 20 + kt * 8 + t;
                MMAH(c_[nt], aQ[kt], S[kw], S[kw + 4]);
            }
        }
        // ---- bias add + exp2, all in half2 ----
        const uint32_t biA = sb + (bb + BIAS_W + (w * 16 + g) * 20) * 4;
        const uint32_t biB = biA + 8 * 20 * 4;
        uint32_t PH[8], PH2[8];
#pragma unroll
        for (int nt = 0; nt < 8; nt++) {
            uint16_t u0, u1;
            asm volatile("ld.shared.u16 %0, [%1];" : "=h"(u0) : "r"(biA + nt * 8 + 2 * t));
            asm volatile("ld.shared.u16 %0, [%1];" : "=h"(u1) : "r"(biB + nt * 8 + 2 * t));
            uint32_t hb0, hb1;
            asm volatile("cvt.rn.f16x2.e4m3x2 %0, %1;" : "=r"(hb0) : "h"(u0));
            asm volatile("cvt.rn.f16x2.e4m3x2 %0, %1;" : "=r"(hb1) : "h"(u1));
            uint32_t s0, s1;
            asm("cvt.rn.f16x2.f32 %0, %1, %2;" : "=r"(s0) : "f"(c_[nt][1]), "f"(c_[nt][0]));
            asm("cvt.rn.f16x2.f32 %0, %1, %2;" : "=r"(s1) : "f"(c_[nt][3]), "f"(c_[nt][2]));
            __half2 e0 = __hadd2(*(__half2*)&s0, *(__half2*)&hb0);
            __half2 e1 = __hadd2(*(__half2*)&s1, *(__half2*)&hb1);
            asm("ex2.approx.f16x2 %0, %1;" : "=r"(PH[nt])  : "r"(bitsh2(e0)));
            asm("ex2.approx.f16x2 %0, %1;" : "=r"(PH2[nt]) : "r"(bitsh2(e1)));
        }
        // ---- PV (+ ones-row MMA accumulating l into O5) ----
#pragma unroll
        for (int u = 0; u < 4; u++) {
            uint32_t aP[4] = {PH[2 * u], PH2[2 * u], PH[2 * u + 1], PH2[2 * u + 1]};
#pragma unroll
            for (int dnt = 0; dnt < 4; dnt++) {
                int vw = bb + V_W + (dnt * 8 + g) * 36 + u * 8 + t;
                MMAH(O[dnt], aP, S[vw], S[vw + 4]);
            }
            int vw5 = bb + V_W + (32 + g) * 36 + u * 8 + t;
            MMAH(O5, aP, S[vw5], S[vw5 + 4]);
        }
        __syncthreads();
    }

    // l lives in quad-lane t=0 (output col 32): broadcast within quad
    const int src = lane & ~3;
    float lA = __shfl_sync(0xffffffffu, O5[0], src);
    float lB = __shfl_sync(0xffffffffu, O5[2], src);
    const float iA = 1.f / lA, iB = 1.f / lB;

    const int b = bh >> 3, h = bh & 7;
    const int nA = rowA & (Nn - 1);
    const size_t baseA = ((size_t)b * Nn + nA) * En + h * Dn;
    const size_t baseB = baseA + 8 * En;
#pragma unroll
    for (int dnt = 0; dnt < 4; dnt++) {
        int dd = dnt * 8 + 2 * t;
        *(uint32_t*)&g_ch[baseA + dd] = bitsh2(__floats2half2_rn(O[dnt][0] * iA, O[dnt][1] * iA));
        *(uint32_t*)&g_ch[baseB + dd] = bitsh2(__floats2half2_rn(O[dnt][2] * iB, O[dnt][3] * iB));
    }
}

// ============================================================================
extern "C" void kernel_launch(void* const* d_in, const int* in_sizes, int n_in,
                              void* d_out, int out_size)
{
    const float* x   = (const float*)d_in[0];
    const float* adj = (const float*)d_in[1];
    const float* Wq  = (const float*)d_in[2];
    const float* bq  = (const float*)d_in[3];
    const float* Wk  = (const float*)d_in[4];
    const float* bk  = (const float*)d_in[5];
    const float* Wv  = (const float*)d_in[6];
    const float* bv  = (const float*)d_in[7];
    const float* Wo  = (const float*)d_in[8];
    const float* bo  = (const float*)d_in[9];
    const float* Wa  = (const float*)d_in[10];
    const float* ba  = (const float*)d_in[11];
    float* out = (float*)d_out;

    // one-time side-stream + events + smem attribute (host-side; no device alloc)
    static cudaStream_t s2 = nullptr;
    static cudaEvent_t evFork = nullptr, evB1 = nullptr, evB2 = nullptr;
    if (s2 == nullptr) {
        cudaStreamCreateWithFlags(&s2, cudaStreamNonBlocking);
        cudaEventCreateWithFlags(&evFork, cudaEventDisableTiming);
        cudaEventCreateWithFlags(&evB1, cudaEventDisableTiming);
        cudaEventCreateWithFlags(&evB2, cudaEventDisableTiming);
        cudaFuncSetAttribute(attn_tc, cudaFuncAttributeMaxDynamicSharedMemorySize,
                             ATTN_SMEM_BYTES);
    }

    // fork: bias_pre in two batch halves on side stream
    cudaEventRecord(evFork, 0);
    cudaStreamWaitEvent(s2, evFork, 0);
    bias_pre<<<(Bn / 2) * Nn, 256, 0, s2>>>(adj, Wa, ba, 0);
    cudaEventRecord(evB1, s2);
    bias_pre<<<(Bn / 2) * Nn, 256, 0, s2>>>(adj, Wa, ba, 4);
    cudaEventRecord(evB2, s2);

    // main chain: converts + QKV GEMM (V transposed+converted in epilogue)
    convert_x<<<(Bn * Nn * En / 4) / 256, 256>>>(x);
    convert_wt<<<4 * 64, 256>>>(Wq, Wk, Wv, Wo);

    dim3 gq(En / 64, (Bn * Nn) / 128, 3);
    gemm_tc<0><<<gq, 256>>>(bq, bk, bv, nullptr, nullptr);

    // attention half 1 (overlaps bias_pre half 2 on s2)
    cudaStreamWaitEvent(0, evB1, 0);
    dim3 ga(Nn / 128, Hn, Bn / 2);
    attn_tc<<<ga, 256, ATTN_SMEM_BYTES>>>(0);

    // attention half 2
    cudaStreamWaitEvent(0, evB2, 0);
    attn_tc<<<ga, 256, ATTN_SMEM_BYTES>>>(4);

    // output projection + residual
    dim3 go(En / 64, (Bn * Nn) / 128);
    gemm_tc<1><<<go, 256>>>(bo, bo, bo, x, out);
}

// round 16
// speedup vs baseline: 1.6534x; 1.0116x over previous
#include <cuda_runtime.h>
#include <cuda_bf16.h>
#include <cuda_fp16.h>
#include <cstdint>

#define Bn 8
#define Nn 1024
#define En 256
#define Hn 8
#define Dn 32
#define Cn 4

#define QSZ (Bn * Hn * Nn * Dn)            // 2M elems
__device__ __half g_xh[Bn * Nn * En];
__device__ __half g_qh[QSZ];
__device__ __half g_kh[QSZ];
__device__ __half g_vth[QSZ];              // [B,H,D,N]
__device__ __half g_ch[Bn * Nn * En];      // ctx row-major
__device__ __half g_wth[4 * En * En];      // W^T: q,k,v,o
__device__ uint8_t g_bias8[(size_t)Bn * Hn * Nn * Nn]; // 67MB e4m3, log2e-scaled

#define SCALEQ 0.25506807163967554f   // 1/sqrt(32) * log2e
#define LOG2E  1.4426950408889634f

__device__ __forceinline__ uint32_t bitsh2(__half2 v) {
    return *reinterpret_cast<uint32_t*>(&v);
}
__device__ __forceinline__ uint2 pack4h(float a, float b, float c, float d) {
    uint2 r;
    r.x = bitsh2(__floats2half2_rn(a, b));
    r.y = bitsh2(__floats2half2_rn(c, d));
    return r;
}
__device__ __forceinline__ uint32_t smem_u32(const void* p) {
    uint32_t a;
    asm("{ .reg .u64 t; cvta.to.shared.u64 t, %1; cvt.u32.u64 %0, t; }" : "=r"(a) : "l"(p));
    return a;
}
// pack two floats -> e4m3x2 (lo byte = second operand)
__device__ __forceinline__ uint16_t pk_e4m3(float hi, float lo) {
    uint16_t r;
    asm("cvt.rn.satfinite.e4m3x2.f32 %0, %1, %2;" : "=h"(r) : "f"(hi), "f"(lo));
    return r;
}

#define CP_A16(d, s) asm volatile("cp.async.cg.shared.global [%0], [%1], 16;" :: "r"(d), "l"(s) : "memory")
#define CP_COMMIT()  asm volatile("cp.async.commit_group;" ::: "memory")
#define CP_WAIT0()   asm volatile("cp.async.wait_group 0;" ::: "memory")
#define CP_WAIT1()   asm volatile("cp.async.wait_group 1;" ::: "memory")

#define MMAH(c, a, b0, b1)                                                    \
    asm volatile("mma.sync.aligned.m16n8k16.row.col.f32.f16.f16.f32 "         \
        "{%0,%1,%2,%3}, {%4,%5,%6,%7}, {%8,%9}, {%0,%1,%2,%3};"               \
        : "+f"((c)[0]), "+f"((c)[1]), "+f"((c)[2]), "+f"((c)[3])              \
        : "r"((a)[0]), "r"((a)[1]), "r"((a)[2]), "r"((a)[3]), "r"(b0), "r"(b1))

// ============================================================================
// fused converts: blocks [0,2048) -> x->fp16 ; blocks [2048,2304) -> W^T fp16
// ============================================================================
__global__ __launch_bounds__(256)
void convert_fused(const float* __restrict__ x,
                   const float* __restrict__ W0, const float* __restrict__ W1,
                   const float* __restrict__ W2, const float* __restrict__ W3)
{
    const int tid = threadIdx.x;
    if (blockIdx.x < 2048) {
        int i = blockIdx.x * 256 + tid;       // per float4
        float4 v = ((const float4*)x)[i];
        ((uint2*)g_xh)[i] = pack4h(v.x, v.y, v.z, v.w);
        return;
    }
    __shared__ float T[32][33];
    const int bid = blockIdx.x - 2048;
    const int z = bid >> 6;
    const int tile = bid & 63;
    const int k0 = (tile >> 3) * 32;
    const int n0 = (tile & 7) * 32;
    const float* W = (z == 0) ? W0 : (z == 1) ? W1 : (z == 2) ? W2 : W3;
    {
        int r = tid >> 3, c4 = tid & 7;
        float4 v = *(const float4*)&W[(k0 + r) * En + n0 + c4 * 4];
        T[r][c4 * 4 + 0] = v.x; T[r][c4 * 4 + 1] = v.y;
        T[r][c4 * 4 + 2] = v.z; T[r][c4 * 4 + 3] = v.w;
    }
    __syncthreads();
    {
        int r = tid >> 3, c4 = tid & 7;
        int off = z * En * En + (n0 + r) * En + k0 + c4 * 4;
        *(uint2*)&g_wth[off] = pack4h(T[c4 * 4 + 0][r], T[c4 * 4 + 1][r],
                                      T[c4 * 4 + 2][r], T[c4 * 4 + 3][r]);
    }
}

// ============================================================================
// fp16 tensor-core GEMM, cp.async 3-stage pipelined (one sync per chunk).
// MODE 0: QKV (z=blockIdx.z; epilogue -> fp16 Q(scaled)/K; V transposed+fp16
//          through smem restage -> g_vth [B,H,D,N])
// MODE 1: out-proj (A=g_ch, W slot 3; epilogue -> +bo +x -> out fp32)
// ============================================================================
#define GBUF_W 3840          // per buffer: A@0 (2560) + B@2560 (1280)
#define GB_OFF 2560

template <int MODE>
__global__ __launch_bounds__(256)
void gemm_tc(const float* __restrict__ bias0, const float* __restrict__ bias1,
             const float* __restrict__ bias2,
             const float* __restrict__ X, float* __restrict__ OutR)
{
    __shared__ __align__(16) uint32_t S[3 * GBUF_W];   // 45 KB
    const uint32_t sb = smem_u32(S);
    const int tid = threadIdx.x;
    const int w = tid >> 5, lane = tid & 31;
    const int g = lane >> 2, t = lane & 3;
    const int row0 = blockIdx.y * 128;
    const int col0 = blockIdx.x * 64;
    const int z = (MODE == 0) ? blockIdx.z : 3;

    const uint4* a4p = (const uint4*)((MODE == 0) ? g_xh : g_ch);
    const uint4* b4p = (const uint4*)(g_wth + z * En * En);

    float c_[8][4] = {};

    const int a_row = tid >> 1;          // 0..127
    const int a_c4 = (tid & 1) * 2;      // uint4 col 0/2
    const int b_row = tid >> 2;          // 0..63
    const int b_c4 = tid & 3;

    auto stage = [&](int kc, int bb) {
        size_t siA = (size_t)(row0 + a_row) * 32 + kc * 4 + a_c4;
        CP_A16(sb + (bb + a_row * 20 + a_c4 * 4) * 4, a4p + siA);
        CP_A16(sb + (bb + a_row * 20 + (a_c4 + 1) * 4) * 4, a4p + siA + 1);
        size_t siB = (size_t)(col0 + b_row) * 32 + kc * 4 + b_c4;
        CP_A16(sb + (bb + GB_OFF + b_row * 20 + b_c4 * 4) * 4, b4p + siB);
        CP_COMMIT();
    };

    stage(0, 0);
    stage(1, GBUF_W);
    for (int kc = 0; kc < 8; kc++) {
        if (kc + 1 < 8) CP_WAIT1(); else CP_WAIT0();
        __syncthreads();
        if (kc + 2 < 8) stage(kc + 2, ((kc + 2) % 3) * GBUF_W);
        const int bb = (kc % 3) * GBUF_W;
#pragma unroll
        for (int kt = 0; kt < 2; kt++) {
            const int aw = bb + (w * 16 + g) * 20 + kt * 8 + t;
            uint32_t a[4];
            a[0] = S[aw];       a[1] = S[aw + 160];
            a[2] = S[aw + 4];   a[3] = S[aw + 164];
#pragma unroll
            for (int nt = 0; nt < 8; nt++) {
                const int kw = bb + GB_OFF + (nt * 8 + g) * 20 + kt * 8 + t;
                MMAH(c_[nt], a, S[kw], S[kw + 4]);
            }
        }
    }
    __syncthreads();

    const int m = row0 + w * 16 + g;
    if (MODE == 0) {
        const float* bias = (z == 0) ? bias0 : (z == 1) ? bias1 : bias2;
        const int b = row0 >> 10, n0 = row0 & 1023;
        const int n = m & 1023;
        if (z < 2) {
#pragma unroll
            for (int nt = 0; nt < 8; nt++) {
                int col = col0 + nt * 8 + 2 * t;
                float bz0 = bias[col], bz1 = bias[col + 1];
                float v0 = c_[nt][0] + bz0, v1 = c_[nt][1] + bz1;
                float v2 = c_[nt][2] + bz0, v3 = c_[nt][3] + bz1;
                int h = col >> 5, dd = col & 31;
                size_t oA = ((size_t)(b * Hn + h) * Nn + n) * Dn + dd;
                size_t oB = oA + 8 * Dn;
                if (z == 0) {
                    v0 *= SCALEQ; v1 *= SCALEQ; v2 *= SCALEQ; v3 *= SCALEQ;
                    *(uint32_t*)&g_qh[oA] = bitsh2(__floats2half2_rn(v0, v1));
                    *(uint32_t*)&g_qh[oB] = bitsh2(__floats2half2_rn(v2, v3));
                } else {
                    *(uint32_t*)&g_kh[oA] = bitsh2(__floats2half2_rn(v0, v1));
                    *(uint32_t*)&g_kh[oB] = bitsh2(__floats2half2_rn(v2, v3));
                }
            }
        } else {
            // V: transpose through smem (k-loop done; S reusable) -> g_vth [B,H,D,N]
            __half* S2 = (__half*)S;
            const int lr = w * 16 + g;
#pragma unroll
            for (int nt = 0; nt < 8; nt++) {
                int lc = nt * 8 + 2 * t;
                int col = col0 + lc;
                float bz0 = bias[col], bz1 = bias[col + 1];
                S2[lc * 136 + lr]           = __float2half_rn(c_[nt][0] + bz0);
                S2[(lc + 1) * 136 + lr]     = __float2half_rn(c_[nt][1] + bz1);
                S2[lc * 136 + lr + 8]       = __float2half_rn(c_[nt][2] + bz0);
                S2[(lc + 1) * 136 + lr + 8] = __float2half_rn(c_[nt][3] + bz1);
            }
            __syncthreads();
            const int colx = tid >> 2, seg = tid & 3;
            const int gc = col0 + colx;
            const int h = gc >> 5, dd = gc & 31;
            size_t dst = ((size_t)(b * Hn + h) * Dn + dd) * Nn + n0 + seg * 32;
            const uint4* sp = (const uint4*)&S2[colx * 136 + seg * 32];
            uint4* dp = (uint4*)&g_vth[dst];
            dp[0] = sp[0]; dp[1] = sp[1]; dp[2] = sp[2]; dp[3] = sp[3];
        }
    } else {
#pragma unroll
        for (int nt = 0; nt < 8; nt++) {
            int col = col0 + nt * 8 + 2 * t;
            float bz0 = bias0[col], bz1 = bias0[col + 1];
            float2 xA = *(const float2*)&X[(size_t)m * En + col];
            float2 xB = *(const float2*)&X[(size_t)(m + 8) * En + col];
            float2 oA = {c_[nt][0] + bz0 + xA.x, c_[nt][1] + bz1 + xA.y};
            float2 oB = {c_[nt][2] + bz0 + xB.x, c_[nt][3] + bz1 + xB.y};
            *(float2*)&OutR[(size_t)m * En + col] = oA;
            *(float2*)&OutR[(size_t)(m + 8) * En + col] = oB;
        }
    }
}

// ============================================================================
// bias precompute -> e4m3 fp8, log2e-scaled (full batch).
// ============================================================================
__global__ __launch_bounds__(256)
void bias_pre(const float* __restrict__ adj, const float* __restrict__ Wa,
              const float* __restrict__ ba)
{
    __shared__ float ws[Cn * Hn];
    __shared__ float offs[Hn];
    const int tid = threadIdx.x;
    if (tid < Cn * Hn) ws[tid] = Wa[tid] * LOG2E;   // ws[c*Hn+h]
    if (tid < Hn) offs[tid] = ba[tid] * LOG2E;
    __syncthreads();

    const int b = blockIdx.x >> 10;
    const int i = blockIdx.x & 1023;
    const float4* a4 = (const float4*)&adj[(size_t)(b * Nn + i) * Nn * Cn];
#pragma unroll
    for (int r = 0; r < 2; r++) {
        int j = (tid + r * 256) * 2;
        float4 x0 = __ldcs(a4 + j);
        float4 x1 = __ldcs(a4 + j + 1);
#pragma unroll 1
        for (int h = 0; h < Hn; h++) {
            float w0 = ws[h], w1 = ws[8 + h], w2 = ws[16 + h], w3 = ws[24 + h];
            float o = offs[h];
            float v0 = o + x0.x * w0 + x0.y * w1 + x0.z * w2 + x0.w * w3;
            float v1 = o + x1.x * w0 + x1.y * w1 + x1.z * w2 + x1.w * w3;
            __stcs((uint16_t*)(g_bias8 + ((size_t)((b * Hn + h) * Nn + i)) * Nn + j),
                   pk_e4m3(v1, v0));
        }
    }
}

// ============================================================================
// fp16 tensor-core flash attention; fp8 bias; half2 softmax; l via ones-row MMA.
// 3-stage cp.async pipeline (one sync per tile).
// Per buffer (u32): K@0 (1280), V^T@1280 (40x36=1440; rows 32..39 ones/zeros),
// bias8@2720 (128x20=2560) = 5280.  3 buffers = 63,360 B.
// ============================================================================
#define ABUF_W 5280
#define K_W 0
#define V_W 1280
#define BIAS_W 2720
#define ATTN_SMEM_BYTES (3 * ABUF_W * 4)

__global__ __launch_bounds__(256)
void attn_tc()
{
    extern __shared__ __align__(16) uint32_t S[];
    const uint32_t sb = smem_u32(S);
    const int tid = threadIdx.x;
    const int w = tid >> 5, lane = tid & 31;
    const int g = lane >> 2, t = lane & 3;
    const int i0 = blockIdx.x * 128;
    const int bh = blockIdx.z * Hn + blockIdx.y;

    const uint32_t* q32 = (const uint32_t*)g_qh;
    const int rowA = bh * Nn + i0 + w * 16 + g;
    const int rowB = rowA + 8;
    uint32_t aQ[2][4];
#pragma unroll
    for (int kt = 0; kt < 2; kt++) {
        aQ[kt][0] = q32[rowA * 16 + kt * 8 + t];
        aQ[kt][1] = q32[rowB * 16 + kt * 8 + t];
        aQ[kt][2] = q32[rowA * 16 + kt * 8 + 4 + t];
        aQ[kt][3] = q32[rowB * 16 + kt * 8 + 4 + t];
    }

    float O[4][4] = {};
    float O5[4] = {};          // l accumulator (ones column)

    const uint4* k4p = (const uint4*)g_kh;
    const uint4* v4p = (const uint4*)g_vth;
    const uint4* b84 = (const uint4*)g_bias8;

    const int k_row = tid >> 2, k_c = tid & 3;
    const int v_d = tid >> 3, v_c = tid & 7;

    // init ones/zero rows 32..39 of V region in all 3 buffers (cp.async never
    // touches them); the first in-loop __syncthreads() publishes them.
#pragma unroll
    for (int bbi = 0; bbi < 3; bbi++) {
        int base = bbi * ABUF_W + V_W + 32 * 36;
        for (int idx = tid; idx < 8 * 36; idx += 256) {
            int rrow = idx / 36;
            S[base + idx] = (rrow == 0) ? 0x3C003C00u : 0u;   // half2(1,1) : 0
        }
    }

    auto stage = [&](int jt, int bb) {
        const int j0 = jt * 64;
        CP_A16(sb + (bb + K_W + k_row * 20 + k_c * 4) * 4,
               k4p + (bh * Nn + j0 + k_row) * 4 + k_c);
        CP_A16(sb + (bb + V_W + v_d * 36 + v_c * 4) * 4,
               v4p + (bh * Dn + v_d) * 128 + jt * 8 + v_c);
        // bias8: 128 rows x 4 uint4 (64 B/row), smem pitch 20 words (80 B)
#pragma unroll
        for (int r = 0; r < 2; r++) {
            int idx = tid + r * 256;
            int row = idx >> 2, c = idx & 3;
            CP_A16(sb + (bb + BIAS_W + row * 20 + c * 4) * 4,
                   b84 + ((size_t)(bh * Nn) + i0 + row) * 64 + jt * 4 + c);
        }
        CP_COMMIT();
    };

    stage(0, 0);
    stage(1, ABUF_W);
    for (int jt = 0; jt < 16; jt++) {
        if (jt + 1 < 16) CP_WAIT1(); else CP_WAIT0();
        __syncthreads();
        if (jt + 2 < 16) stage(jt + 2, ((jt + 2) % 3) * ABUF_W);
        const int bb = (jt % 3) * ABUF_W;

        // ---- QK^T ----
        float c_[8][4] = {};
#pragma unroll
        for (int nt = 0; nt < 8; nt++) {
#pragma unroll
            for (int kt = 0; kt < 2; kt++) {
                int kw = bb + K_W + (nt * 8 + g) * 20 + kt * 8 + t;
                MMAH(c_[nt], aQ[kt], S[kw], S[kw + 4]);
            }
        }
        // ---- bias add + exp2, all in half2 ----
        const uint32_t biA = sb + (bb + BIAS_W + (w * 16 + g) * 20) * 4;
        const uint32_t biB = biA + 8 * 20 * 4;
        uint32_t PH[8], PH2[8];
#pragma unroll
        for (int nt = 0; nt < 8; nt++) {
            uint16_t u0, u1;
            asm volatile("ld.shared.u16 %0, [%1];" : "=h"(u0) : "r"(biA + nt * 8 + 2 * t));
            asm volatile("ld.shared.u16 %0, [%1];" : "=h"(u1) : "r"(biB + nt * 8 + 2 * t));
            uint32_t hb0, hb1;
            asm volatile("cvt.rn.f16x2.e4m3x2 %0, %1;" : "=r"(hb0) : "h"(u0));
            asm volatile("cvt.rn.f16x2.e4m3x2 %0, %1;" : "=r"(hb1) : "h"(u1));
            uint32_t s0, s1;
            asm("cvt.rn.f16x2.f32 %0, %1, %2;" : "=r"(s0) : "f"(c_[nt][1]), "f"(c_[nt][0]));
            asm("cvt.rn.f16x2.f32 %0, %1, %2;" : "=r"(s1) : "f"(c_[nt][3]), "f"(c_[nt][2]));
            __half2 e0 = __hadd2(*(__half2*)&s0, *(__half2*)&hb0);
            __half2 e1 = __hadd2(*(__half2*)&s1, *(__half2*)&hb1);
            asm("ex2.approx.f16x2 %0, %1;" : "=r"(PH[nt])  : "r"(bitsh2(e0)));
            asm("ex2.approx.f16x2 %0, %1;" : "=r"(PH2[nt]) : "r"(bitsh2(e1)));
        }
        // ---- PV (+ ones-row MMA accumulating l into O5) ----
#pragma unroll
        for (int u = 0; u < 4; u++) {
            uint32_t aP[4] = {PH[2 * u], PH2[2 * u], PH[2 * u + 1], PH2[2 * u + 1]};
#pragma unroll
            for (int dnt = 0; dnt < 4; dnt++) {
                int vw = bb + V_W + (dnt * 8 + g) * 36 + u * 8 + t;
                MMAH(O[dnt], aP, S[vw], S[vw + 4]);
            }
            int vw5 = bb + V_W + (32 + g) * 36 + u * 8 + t;
            MMAH(O5, aP, S[vw5], S[vw5 + 4]);
        }
    }

    // l lives in quad-lane t=0 (output col 32): broadcast within quad
    const int src = lane & ~3;
    float lA = __shfl_sync(0xffffffffu, O5[0], src);
    float lB = __shfl_sync(0xffffffffu, O5[2], src);
    const float iA = 1.f / lA, iB = 1.f / lB;

    const int b = bh >> 3, h = bh & 7;
    const int nA = rowA & (Nn - 1);
    const size_t baseA = ((size_t)b * Nn + nA) * En + h * Dn;
    const size_t baseB = baseA + 8 * En;
#pragma unroll
    for (int dnt = 0; dnt < 4; dnt++) {
        int dd = dnt * 8 + 2 * t;
        *(uint32_t*)&g_ch[baseA + dd] = bitsh2(__floats2half2_rn(O[dnt][0] * iA, O[dnt][1] * iA));
        *(uint32_t*)&g_ch[baseB + dd] = bitsh2(__floats2half2_rn(O[dnt][2] * iB, O[dnt][3] * iB));
    }
}

// ============================================================================
extern "C" void kernel_launch(void* const* d_in, const int* in_sizes, int n_in,
                              void* d_out, int out_size)
{
    const float* x   = (const float*)d_in[0];
    const float* adj = (const float*)d_in[1];
    const float* Wq  = (const float*)d_in[2];
    const float* bq  = (const float*)d_in[3];
    const float* Wk  = (const float*)d_in[4];
    const float* bk  = (const float*)d_in[5];
    const float* Wv  = (const float*)d_in[6];
    const float* bv  = (const float*)d_in[7];
    const float* Wo  = (const float*)d_in[8];
    const float* bo  = (const float*)d_in[9];
    const float* Wa  = (const float*)d_in[10];
    const float* ba  = (const float*)d_in[11];
    float* out = (float*)d_out;

    // one-time side-stream + events + smem attribute (host-side; no device alloc)
    static cudaStream_t s2 = nullptr;
    static cudaEvent_t evFork = nullptr, evB = nullptr;
    if (s2 == nullptr) {
        cudaStreamCreateWithFlags(&s2, cudaStreamNonBlocking);
        cudaEventCreateWithFlags(&evFork, cudaEventDisableTiming);
        cudaEventCreateWithFlags(&evB, cudaEventDisableTiming);
        cudaFuncSetAttribute(attn_tc, cudaFuncAttributeMaxDynamicSharedMemorySize,
                             ATTN_SMEM_BYTES);
    }

    // fork: bias_pre (full batch) on side stream, hidden behind converts+gemm0
    cudaEventRecord(evFork, 0);
    cudaStreamWaitEvent(s2, evFork, 0);
    bias_pre<<<Bn * Nn, 256, 0, s2>>>(adj, Wa, ba);
    cudaEventRecord(evB, s2);

    // main chain: fused converts + QKV GEMM (V transposed+converted in epilogue)
    convert_fused<<<2048 + 256, 256>>>(x, Wq, Wk, Wv, Wo);

    dim3 gq(En / 64, (Bn * Nn) / 128, 3);
    gemm_tc<0><<<gq, 256>>>(bq, bk, bv, nullptr, nullptr);

    // join: attention needs g_bias8
    cudaStreamWaitEvent(0, evB, 0);
    dim3 ga(Nn / 128, Hn, Bn);
    attn_tc<<<ga, 256, ATTN_SMEM_BYTES>>>();

    // output projection + residual
    dim3 go(En / 64, (Bn * Nn) / 128);
    gemm_tc<1><<<go, 256>>>(bo, bo, bo, x, out);
}

// round 17
// speedup vs baseline: 1.6915x; 1.0230x over previous
#include <cuda_runtime.h>
#include <cuda_bf16.h>
#include <cuda_fp16.h>
#include <cstdint>

#define Bn 8
#define Nn 1024
#define En 256
#define Hn 8
#define Dn 32
#define Cn 4

#define QSZ (Bn * Hn * Nn * Dn)            // 2M elems
__device__ __half g_xh[Bn * Nn * En];
__device__ __half g_qh[QSZ];
__device__ __half g_kh[QSZ];
__device__ __half g_vth[QSZ];              // [B,H,D,N]
__device__ __half g_ch[Bn * Nn * En];      // ctx row-major
__device__ __half g_wth[4 * En * En];      // W^T: q,k,v,o
__device__ uint8_t g_bias8[(size_t)Bn * Hn * Nn * Nn]; // 67MB e4m3, log2e-scaled

#define SCALEQ 0.25506807163967554f   // 1/sqrt(32) * log2e
#define LOG2E  1.4426950408889634f

__device__ __forceinline__ uint32_t bitsh2(__half2 v) {
    return *reinterpret_cast<uint32_t*>(&v);
}
__device__ __forceinline__ uint2 pack4h(float a, float b, float c, float d) {
    uint2 r;
    r.x = bitsh2(__floats2half2_rn(a, b));
    r.y = bitsh2(__floats2half2_rn(c, d));
    return r;
}
__device__ __forceinline__ uint32_t smem_u32(const void* p) {
    uint32_t a;
    asm("{ .reg .u64 t; cvta.to.shared.u64 t, %1; cvt.u32.u64 %0, t; }" : "=r"(a) : "l"(p));
    return a;
}
__device__ __forceinline__ uint16_t pk_e4m3(float hi, float lo) {
    uint16_t r;
    asm("cvt.rn.satfinite.e4m3x2.f32 %0, %1, %2;" : "=h"(r) : "f"(hi), "f"(lo));
    return r;
}

#define CP_A16(d, s) asm volatile("cp.async.cg.shared.global [%0], [%1], 16;" :: "r"(d), "l"(s) : "memory")
#define CP_COMMIT()  asm volatile("cp.async.commit_group;" ::: "memory")
#define CP_WAIT0()   asm volatile("cp.async.wait_group 0;" ::: "memory")
#define CP_WAIT1()   asm volatile("cp.async.wait_group 1;" ::: "memory")

#define MMAH(c, a, b0, b1)                                                    \
    asm volatile("mma.sync.aligned.m16n8k16.row.col.f32.f16.f16.f32 "         \
        "{%0,%1,%2,%3}, {%4,%5,%6,%7}, {%8,%9}, {%0,%1,%2,%3};"               \
        : "+f"((c)[0]), "+f"((c)[1]), "+f"((c)[2]), "+f"((c)[3])              \
        : "r"((a)[0]), "r"((a)[1]), "r"((a)[2]), "r"((a)[3]), "r"(b0), "r"(b1))

// ============================================================================
// fused converts: blocks [0,2048) -> x->fp16 ; blocks [2048,2304) -> W^T fp16
// ============================================================================
__global__ __launch_bounds__(256)
void convert_fused(const float* __restrict__ x,
                   const float* __restrict__ W0, const float* __restrict__ W1,
                   const float* __restrict__ W2, const float* __restrict__ W3)
{
    const int tid = threadIdx.x;
    if (blockIdx.x < 2048) {
        int i = blockIdx.x * 256 + tid;       // per float4
        float4 v = ((const float4*)x)[i];
        ((uint2*)g_xh)[i] = pack4h(v.x, v.y, v.z, v.w);
        return;
    }
    __shared__ float T[32][33];
    const int bid = blockIdx.x - 2048;
    const int z = bid >> 6;
    const int tile = bid & 63;
    const int k0 = (tile >> 3) * 32;
    const int n0 = (tile & 7) * 32;
    const float* W = (z == 0) ? W0 : (z == 1) ? W1 : (z == 2) ? W2 : W3;
    {
        int r = tid >> 3, c4 = tid & 7;
        float4 v = *(const float4*)&W[(k0 + r) * En + n0 + c4 * 4];
        T[r][c4 * 4 + 0] = v.x; T[r][c4 * 4 + 1] = v.y;
        T[r][c4 * 4 + 2] = v.z; T[r][c4 * 4 + 3] = v.w;
    }
    __syncthreads();
    {
        int r = tid >> 3, c4 = tid & 7;
        int off = z * En * En + (n0 + r) * En + k0 + c4 * 4;
        *(uint2*)&g_wth[off] = pack4h(T[c4 * 4 + 0][r], T[c4 * 4 + 1][r],
                                      T[c4 * 4 + 2][r], T[c4 * 4 + 3][r]);
    }
}

// ============================================================================
// fp16 tensor-core GEMM, cp.async 3-stage pipelined.
// MODE 0: QKV (z=blockIdx.z; epilogue -> fp16 Q(scaled)/K; V transposed+fp16)
// MODE 1: out-proj (A=g_ch, W slot 3; epilogue -> +bo +x -> out fp32); yoff
//         allows row-half launches.
// ============================================================================
#define GBUF_W 3840          // per buffer: A@0 (2560) + B@2560 (1280)
#define GB_OFF 2560

template <int MODE>
__global__ __launch_bounds__(256)
void gemm_tc(const float* __restrict__ bias0, const float* __restrict__ bias1,
             const float* __restrict__ bias2,
             const float* __restrict__ X, float* __restrict__ OutR, int yoff)
{
    __shared__ __align__(16) uint32_t S[3 * GBUF_W];   // 45 KB
    const uint32_t sb = smem_u32(S);
    const int tid = threadIdx.x;
    const int w = tid >> 5, lane = tid & 31;
    const int g = lane >> 2, t = lane & 3;
    const int row0 = (blockIdx.y + yoff) * 128;
    const int col0 = blockIdx.x * 64;
    const int z = (MODE == 0) ? blockIdx.z : 3;

    const uint4* a4p = (const uint4*)((MODE == 0) ? g_xh : g_ch);
    const uint4* b4p = (const uint4*)(g_wth + z * En * En);

    float c_[8][4] = {};

    const int a_row = tid >> 1;          // 0..127
    const int a_c4 = (tid & 1) * 2;      // uint4 col 0/2
    const int b_row = tid >> 2;          // 0..63
    const int b_c4 = tid & 3;

    auto stage = [&](int kc, int bb) {
        size_t siA = (size_t)(row0 + a_row) * 32 + kc * 4 + a_c4;
        CP_A16(sb + (bb + a_row * 20 + a_c4 * 4) * 4, a4p + siA);
        CP_A16(sb + (bb + a_row * 20 + (a_c4 + 1) * 4) * 4, a4p + siA + 1);
        size_t siB = (size_t)(col0 + b_row) * 32 + kc * 4 + b_c4;
        CP_A16(sb + (bb + GB_OFF + b_row * 20 + b_c4 * 4) * 4, b4p + siB);
        CP_COMMIT();
    };

    stage(0, 0);
    stage(1, GBUF_W);
    for (int kc = 0; kc < 8; kc++) {
        if (kc + 1 < 8) CP_WAIT1(); else CP_WAIT0();
        __syncthreads();
        if (kc + 2 < 8) stage(kc + 2, ((kc + 2) % 3) * GBUF_W);
        const int bb = (kc % 3) * GBUF_W;
#pragma unroll
        for (int kt = 0; kt < 2; kt++) {
            const int aw = bb + (w * 16 + g) * 20 + kt * 8 + t;
            uint32_t a[4];
            a[0] = S[aw];       a[1] = S[aw + 160];
            a[2] = S[aw + 4];   a[3] = S[aw + 164];
#pragma unroll
            for (int nt = 0; nt < 8; nt++) {
                const int kw = bb + GB_OFF + (nt * 8 + g) * 20 + kt * 8 + t;
                MMAH(c_[nt], a, S[kw], S[kw + 4]);
            }
        }
    }
    __syncthreads();

    const int m = row0 + w * 16 + g;
    if (MODE == 0) {
        const float* bias = (z == 0) ? bias0 : (z == 1) ? bias1 : bias2;
        const int b = row0 >> 10, n0 = row0 & 1023;
        const int n = m & 1023;
        if (z < 2) {
#pragma unroll
            for (int nt = 0; nt < 8; nt++) {
                int col = col0 + nt * 8 + 2 * t;
                float bz0 = bias[col], bz1 = bias[col + 1];
                float v0 = c_[nt][0] + bz0, v1 = c_[nt][1] + bz1;
                float v2 = c_[nt][2] + bz0, v3 = c_[nt][3] + bz1;
                int h = col >> 5, dd = col & 31;
                size_t oA = ((size_t)(b * Hn + h) * Nn + n) * Dn + dd;
                size_t oB = oA + 8 * Dn;
                if (z == 0) {
                    v0 *= SCALEQ; v1 *= SCALEQ; v2 *= SCALEQ; v3 *= SCALEQ;
                    *(uint32_t*)&g_qh[oA] = bitsh2(__floats2half2_rn(v0, v1));
                    *(uint32_t*)&g_qh[oB] = bitsh2(__floats2half2_rn(v2, v3));
                } else {
                    *(uint32_t*)&g_kh[oA] = bitsh2(__floats2half2_rn(v0, v1));
                    *(uint32_t*)&g_kh[oB] = bitsh2(__floats2half2_rn(v2, v3));
                }
            }
        } else {
            // V: transpose through smem -> g_vth [B,H,D,N]
            __half* S2 = (__half*)S;
            const int lr = w * 16 + g;
#pragma unroll
            for (int nt = 0; nt < 8; nt++) {
                int lc = nt * 8 + 2 * t;
                int col = col0 + lc;
                float bz0 = bias[col], bz1 = bias[col + 1];
                S2[lc * 136 + lr]           = __float2half_rn(c_[nt][0] + bz0);
                S2[(lc + 1) * 136 + lr]     = __float2half_rn(c_[nt][1] + bz1);
                S2[lc * 136 + lr + 8]       = __float2half_rn(c_[nt][2] + bz0);
                S2[(lc + 1) * 136 + lr + 8] = __float2half_rn(c_[nt][3] + bz1);
            }
            __syncthreads();
            const int colx = tid >> 2, seg = tid & 3;
            const int gc = col0 + colx;
            const int h = gc >> 5, dd = gc & 31;
            size_t dst = ((size_t)(b * Hn + h) * Dn + dd) * Nn + n0 + seg * 32;
            const uint4* sp = (const uint4*)&S2[colx * 136 + seg * 32];
            uint4* dp = (uint4*)&g_vth[dst];
            dp[0] = sp[0]; dp[1] = sp[1]; dp[2] = sp[2]; dp[3] = sp[3];
        }
    } else {
#pragma unroll
        for (int nt = 0; nt < 8; nt++) {
            int col = col0 + nt * 8 + 2 * t;
            float bz0 = bias0[col], bz1 = bias0[col + 1];
            float2 xA = *(const float2*)&X[(size_t)m * En + col];
            float2 xB = *(const float2*)&X[(size_t)(m + 8) * En + col];
            float2 oA = {c_[nt][0] + bz0 + xA.x, c_[nt][1] + bz1 + xA.y};
            float2 oB = {c_[nt][2] + bz0 + xB.x, c_[nt][3] + bz1 + xB.y};
            *(float2*)&OutR[(size_t)m * En + col] = oA;
            *(float2*)&OutR[(size_t)(m + 8) * En + col] = oB;
        }
    }
}

// ============================================================================
// bias precompute -> e4m3 fp8, log2e-scaled (full batch).
// All 4 loads hoisted ahead of compute/stores (MLP=4).
// ============================================================================
__global__ __launch_bounds__(256)
void bias_pre(const float* __restrict__ adj, const float* __restrict__ Wa,
              const float* __restrict__ ba)
{
    __shared__ float ws[Cn * Hn];
    __shared__ float offs[Hn];
    const int tid = threadIdx.x;
    if (tid < Cn * Hn) ws[tid] = Wa[tid] * LOG2E;   // ws[c*Hn+h]
    if (tid < Hn) offs[tid] = ba[tid] * LOG2E;
    __syncthreads();

    const int b = blockIdx.x >> 10;
    const int i = blockIdx.x & 1023;
    const float4* a4 = (const float4*)&adj[(size_t)(b * Nn + i) * Nn * Cn];
    const int j0 = tid * 2;            // r = 0 pair
    const int j1 = (tid + 256) * 2;    // r = 1 pair
    float4 xa0 = __ldcs(a4 + j0);
    float4 xa1 = __ldcs(a4 + j0 + 1);
    float4 xb0 = __ldcs(a4 + j1);
    float4 xb1 = __ldcs(a4 + j1 + 1);
#pragma unroll 1
    for (int h = 0; h < Hn; h++) {
        float w0 = ws[h], w1 = ws[8 + h], w2 = ws[16 + h], w3 = ws[24 + h];
        float o = offs[h];
        float va0 = o + xa0.x * w0 + xa0.y * w1 + xa0.z * w2 + xa0.w * w3;
        float va1 = o + xa1.x * w0 + xa1.y * w1 + xa1.z * w2 + xa1.w * w3;
        float vb0 = o + xb0.x * w0 + xb0.y * w1 + xb0.z * w2 + xb0.w * w3;
        float vb1 = o + xb1.x * w0 + xb1.y * w1 + xb1.z * w2 + xb1.w * w3;
        uint8_t* rowp = g_bias8 + ((size_t)((b * Hn + h) * Nn + i)) * Nn;
        __stcs((uint16_t*)(rowp + j0), pk_e4m3(va1, va0));
        __stcs((uint16_t*)(rowp + j1), pk_e4m3(vb1, vb0));
    }
}

// ============================================================================
// fp16 tensor-core flash attention; fp8 bias; half2 softmax; l via ones-row MMA.
// 3-stage cp.async pipeline.  Half-batch per launch (b0) for tail overlap.
// Per buffer (u32): K@0 (1280), V^T@1280 (40x36=1440; rows 32..39 ones/zeros),
// bias8@2720 (128x20=2560) = 5280.  3 buffers = 63,360 B.
// ============================================================================
#define ABUF_W 5280
#define K_W 0
#define V_W 1280
#define BIAS_W 2720
#define ATTN_SMEM_BYTES (3 * ABUF_W * 4)

__global__ __launch_bounds__(256)
void attn_tc(int b0)
{
    extern __shared__ __align__(16) uint32_t S[];
    const uint32_t sb = smem_u32(S);
    const int tid = threadIdx.x;
    const int w = tid >> 5, lane = tid & 31;
    const int g = lane >> 2, t = lane & 3;
    const int i0 = blockIdx.x * 128;
    const int bh = (b0 + blockIdx.z) * Hn + blockIdx.y;

    const uint32_t* q32 = (const uint32_t*)g_qh;
    const int rowA = bh * Nn + i0 + w * 16 + g;
    const int rowB = rowA + 8;
    uint32_t aQ[2][4];
#pragma unroll
    for (int kt = 0; kt < 2; kt++) {
        aQ[kt][0] = q32[rowA * 16 + kt * 8 + t];
        aQ[kt][1] = q32[rowB * 16 + kt * 8 + t];
        aQ[kt][2] = q32[rowA * 16 + kt * 8 + 4 + t];
        aQ[kt][3] = q32[rowB * 16 + kt * 8 + 4 + t];
    }

    float O[4][4] = {};
    float O5[4] = {};          // l accumulator (ones column)

    const uint4* k4p = (const uint4*)g_kh;
    const uint4* v4p = (const uint4*)g_vth;
    const uint4* b84 = (const uint4*)g_bias8;

    const int k_row = tid >> 2, k_c = tid & 3;
    const int v_d = tid >> 3, v_c = tid & 7;

    // init ones/zero rows 32..39 of V region in all 3 buffers
#pragma unroll
    for (int bbi = 0; bbi < 3; bbi++) {
        int base = bbi * ABUF_W + V_W + 32 * 36;
        for (int idx = tid; idx < 8 * 36; idx += 256) {
            int rrow = idx / 36;
            S[base + idx] = (rrow == 0) ? 0x3C003C00u : 0u;   // half2(1,1) : 0
        }
    }

    auto stage = [&](int jt, int bb) {
        const int j0 = jt * 64;
        CP_A16(sb + (bb + K_W + k_row * 20 + k_c * 4) * 4,
               k4p + (bh * Nn + j0 + k_row) * 4 + k_c);
        CP_A16(sb + (bb + V_W + v_d * 36 + v_c * 4) * 4,
               v4p + (bh * Dn + v_d) * 128 + jt * 8 + v_c);
#pragma unroll
        for (int r = 0; r < 2; r++) {
            int idx = tid + r * 256;
            int row = idx >> 2, c = idx & 3;
            CP_A16(sb + (bb + BIAS_W + row * 20 + c * 4) * 4,
                   b84 + ((size_t)(bh * Nn) + i0 + row) * 64 + jt * 4 + c);
        }
        CP_COMMIT();
    };

    stage(0, 0);
    stage(1, ABUF_W);
    for (int jt = 0; jt < 16; jt++) {
        if (jt + 1 < 16) CP_WAIT1(); else CP_WAIT0();
        __syncthreads();
        if (jt + 2 < 16) stage(jt + 2, ((jt + 2) % 3) * ABUF_W);
        const int bb = (jt % 3) * ABUF_W;

        // ---- QK^T ----
        float c_[8][4] = {};
#pragma unroll
        for (int nt = 0; nt < 8; nt++) {
#pragma unroll
            for (int kt = 0; kt < 2; kt++) {
                int kw = bb + K_W + (nt * 8 + g) * 20 + kt * 8 + t;
                MMAH(c_[nt], aQ[kt], S[kw], S[kw + 4]);
            }
        }
        // ---- bias add + exp2, all in half2 ----
        const uint32_t biA = sb + (bb + BIAS_W + (w * 16 + g) * 20) * 4;
        const uint32_t biB = biA + 8 * 20 * 4;
        uint32_t PH[8], PH2[8];
#pragma unroll
        for (int nt = 0; nt < 8; nt++) {
            uint16_t u0, u1;
            asm volatile("ld.shared.u16 %0, [%1];" : "=h"(u0) : "r"(biA + nt * 8 + 2 * t));
            asm volatile("ld.shared.u16 %0, [%1];" : "=h"(u1) : "r"(biB + nt * 8 + 2 * t));
            uint32_t hb0, hb1;
            asm volatile("cvt.rn.f16x2.e4m3x2 %0, %1;" : "=r"(hb0) : "h"(u0));
            asm volatile("cvt.rn.f16x2.e4m3x2 %0, %1;" : "=r"(hb1) : "h"(u1));
            uint32_t s0, s1;
            asm("cvt.rn.f16x2.f32 %0, %1, %2;" : "=r"(s0) : "f"(c_[nt][1]), "f"(c_[nt][0]));
            asm("cvt.rn.f16x2.f32 %0, %1, %2;" : "=r"(s1) : "f"(c_[nt][3]), "f"(c_[nt][2]));
            __half2 e0 = __hadd2(*(__half2*)&s0, *(__half2*)&hb0);
            __half2 e1 = __hadd2(*(__half2*)&s1, *(__half2*)&hb1);
            asm("ex2.approx.f16x2 %0, %1;" : "=r"(PH[nt])  : "r"(bitsh2(e0)));
            asm("ex2.approx.f16x2 %0, %1;" : "=r"(PH2[nt]) : "r"(bitsh2(e1)));
        }
        // ---- PV (+ ones-row MMA accumulating l into O5) ----
#pragma unroll
        for (int u = 0; u < 4; u++) {
            uint32_t aP[4] = {PH[2 * u], PH2[2 * u], PH[2 * u + 1], PH2[2 * u + 1]};
#pragma unroll
            for (int dnt = 0; dnt < 4; dnt++) {
                int vw = bb + V_W + (dnt * 8 + g) * 36 + u * 8 + t;
                MMAH(O[dnt], aP, S[vw], S[vw + 4]);
            }
            int vw5 = bb + V_W + (32 + g) * 36 + u * 8 + t;
            MMAH(O5, aP, S[vw5], S[vw5 + 4]);
        }
    }

    // l lives in quad-lane t=0 (output col 32): broadcast within quad
    const int src = lane & ~3;
    float lA = __shfl_sync(0xffffffffu, O5[0], src);
    float lB = __shfl_sync(0xffffffffu, O5[2], src);
    const float iA = 1.f / lA, iB = 1.f / lB;

    const int b = bh >> 3, h = bh & 7;
    const int nA = rowA & (Nn - 1);
    const size_t baseA = ((size_t)b * Nn + nA) * En + h * Dn;
    const size_t baseB = baseA + 8 * En;
#pragma unroll
    for (int dnt = 0; dnt < 4; dnt++) {
        int dd = dnt * 8 + 2 * t;
        *(uint32_t*)&g_ch[baseA + dd] = bitsh2(__floats2half2_rn(O[dnt][0] * iA, O[dnt][1] * iA));
        *(uint32_t*)&g_ch[baseB + dd] = bitsh2(__floats2half2_rn(O[dnt][2] * iB, O[dnt][3] * iB));
    }
}

// ============================================================================
extern "C" void kernel_launch(void* const* d_in, const int* in_sizes, int n_in,
                              void* d_out, int out_size)
{
    const float* x   = (const float*)d_in[0];
    const float* adj = (const float*)d_in[1];
    const float* Wq  = (const float*)d_in[2];
    const float* bq  = (const float*)d_in[3];
    const float* Wk  = (const float*)d_in[4];
    const float* bk  = (const float*)d_in[5];
    const float* Wv  = (const float*)d_in[6];
    const float* bv  = (const float*)d_in[7];
    const float* Wo  = (const float*)d_in[8];
    const float* bo  = (const float*)d_in[9];
    const float* Wa  = (const float*)d_in[10];
    const float* ba  = (const float*)d_in[11];
    float* out = (float*)d_out;

    // one-time side-stream + events + smem attribute (host-side; no device alloc)
    static cudaStream_t s2 = nullptr;
    static cudaEvent_t evFork = nullptr, evB = nullptr, evA1 = nullptr, evG1 = nullptr;
    if (s2 == nullptr) {
        cudaStreamCreateWithFlags(&s2, cudaStreamNonBlocking);
        cudaEventCreateWithFlags(&evFork, cudaEventDisableTiming);
        cudaEventCreateWithFlags(&evB, cudaEventDisableTiming);
        cudaEventCreateWithFlags(&evA1, cudaEventDisableTiming);
        cudaEventCreateWithFlags(&evG1, cudaEventDisableTiming);
        cudaFuncSetAttribute(attn_tc, cudaFuncAttributeMaxDynamicSharedMemorySize,
                             ATTN_SMEM_BYTES);
    }

    // fork: bias_pre (full batch) on side stream, hidden behind converts+gemm0
    cudaEventRecord(evFork, 0);
    cudaStreamWaitEvent(s2, evFork, 0);
    bias_pre<<<Bn * Nn, 256, 0, s2>>>(adj, Wa, ba);
    cudaEventRecord(evB, s2);

    // main chain: fused converts + QKV GEMM (V transposed+converted in epilogue)
    convert_fused<<<2048 + 256, 256>>>(x, Wq, Wk, Wv, Wo);

    dim3 gq(En / 64, (Bn * Nn) / 128, 3);
    gemm_tc<0><<<gq, 256>>>(bq, bk, bv, nullptr, nullptr, 0);

    // attention half 1 (b = 0..3)
    cudaStreamWaitEvent(0, evB, 0);
    dim3 ga(Nn / 128, Hn, Bn / 2);
    attn_tc<<<ga, 256, ATTN_SMEM_BYTES>>>(0);
    cudaEventRecord(evA1, 0);

    // out-proj half 1 on s2 (rows of b 0..3) — overlaps attention half 2
    cudaStreamWaitEvent(s2, evA1, 0);
    dim3 go(En / 64, (Bn * Nn) / 128 / 2);
    gemm_tc<1><<<go, 256, 0, s2>>>(bo, bo, bo, x, out, 0);
    cudaEventRecord(evG1, s2);

    // attention half 2 (b = 4..7)
    attn_tc<<<ga, 256, ATTN_SMEM_BYTES>>>(4);

    // out-proj half 2; join s2
    cudaStreamWaitEvent(0, evG1, 0);
    gemm_tc<1><<<go, 256>>>(bo, bo, bo, x, out, 32);
}